// round 3
// baseline (speedup 1.0000x reference)
#include <cuda_runtime.h>
#include <cuda_bf16.h>
#include <math.h>

// ---------------- problem constants ----------------
#define B_    8
#define S_    256
#define SKV_  1024
#define H_    512
#define NH_   8
#define HD_   64
#define G4_   2048            // 4*H
#define V_    32000
#define BT_   (B_*S_)         // 2048
#define BKV_  (B_*SKV_)       // 8192

// ---------------- device scratch (static; allocation is forbidden) --------
__device__ float    g_xg  [BT_  * (size_t)G4_];   // x@W_ih^T + b_ih + b_hh
__device__ float    g_K   [BKV_ * (size_t)H_];
__device__ float    g_V   [BKV_ * (size_t)H_];
__device__ float    g_H   [BT_  * (size_t)H_];    // hidden history (h_new per step)
__device__ float    g_Q   [BT_  * (size_t)H_];
__device__ float    g_ctx [BT_  * (size_t)H_];
__device__ float    g_outs[BT_  * (size_t)H_];
__device__ float    g_hcur[B_ * H_];
__device__ float    g_att [(size_t)B_ * NH_ * S_ * SKV_];  // 67 MB
__device__ unsigned g_arrive[4];

// ===========================================================================
// Generic fp32 SGEMM:  C[m][n] = sum_k A'[m][k]*Bm[n][k] (+bias1[n]+bias2[n])
// A'[m] = A[gidx[m]] when gidx != nullptr (embedding gather).
// BM=BN=128, BK=16, 256 threads, 8x8 microtile. Requires M%128==0, N%128==0,
// K%16==0 (true at all call sites).
// ===========================================================================
__global__ void __launch_bounds__(256) sgemm_tn(
    int M, int N, int K,
    const float* __restrict__ A, const int* __restrict__ gidx,
    const float* __restrict__ Bm,
    const float* __restrict__ bias1, const float* __restrict__ bias2,
    float* __restrict__ C)
{
    __shared__ float As[16][132];
    __shared__ float Bs[16][132];
    const int tid = threadIdx.x;
    const int m0 = blockIdx.y * 128, n0 = blockIdx.x * 128;
    const int tm = tid >> 4, tn = tid & 15;

    float acc[8][8];
#pragma unroll
    for (int i = 0; i < 8; i++)
#pragma unroll
        for (int j = 0; j < 8; j++) acc[i][j] = 0.f;

    const int id0 = tid * 2, id1 = tid * 2 + 1;
    const int r0 = id0 >> 2, k0 = (id0 & 3) * 4;
    const int r1 = id1 >> 2, k1 = (id1 & 3) * 4;
    int am0 = m0 + r0; if (gidx) am0 = gidx[am0];
    int am1 = m0 + r1; if (gidx) am1 = gidx[am1];
    const float* Arow0 = A  + (size_t)am0 * K;
    const float* Arow1 = A  + (size_t)am1 * K;
    const float* Brow0 = Bm + (size_t)(n0 + r0) * K;
    const float* Brow1 = Bm + (size_t)(n0 + r1) * K;

    for (int kt = 0; kt < K; kt += 16) {
        float4 a0 = *(const float4*)(Arow0 + kt + k0);
        float4 a1 = *(const float4*)(Arow1 + kt + k1);
        float4 b0 = *(const float4*)(Brow0 + kt + k0);
        float4 b1 = *(const float4*)(Brow1 + kt + k1);
        __syncthreads();
        As[k0+0][r0] = a0.x; As[k0+1][r0] = a0.y; As[k0+2][r0] = a0.z; As[k0+3][r0] = a0.w;
        As[k1+0][r1] = a1.x; As[k1+1][r1] = a1.y; As[k1+2][r1] = a1.z; As[k1+3][r1] = a1.w;
        Bs[k0+0][r0] = b0.x; Bs[k0+1][r0] = b0.y; Bs[k0+2][r0] = b0.z; Bs[k0+3][r0] = b0.w;
        Bs[k1+0][r1] = b1.x; Bs[k1+1][r1] = b1.y; Bs[k1+2][r1] = b1.z; Bs[k1+3][r1] = b1.w;
        __syncthreads();
#pragma unroll
        for (int kk = 0; kk < 16; kk++) {
            const float4* Ap = (const float4*)&As[kk][tm * 8];
            const float4* Bp = (const float4*)&Bs[kk][tn * 8];
            float4 av0 = Ap[0], av1 = Ap[1];
            float4 bv0 = Bp[0], bv1 = Bp[1];
            float a[8] = {av0.x,av0.y,av0.z,av0.w, av1.x,av1.y,av1.z,av1.w};
            float b[8] = {bv0.x,bv0.y,bv0.z,bv0.w, bv1.x,bv1.y,bv1.z,bv1.w};
#pragma unroll
            for (int i = 0; i < 8; i++)
#pragma unroll
                for (int j = 0; j < 8; j++) acc[i][j] += a[i] * b[j];
        }
    }

    float bv[8];
#pragma unroll
    for (int j = 0; j < 8; j++) {
        int n = n0 + tn * 8 + j;
        float t = 0.f;
        if (bias1) t += bias1[n];
        if (bias2) t += bias2[n];
        bv[j] = t;
    }
#pragma unroll
    for (int i = 0; i < 8; i++) {
        int m = m0 + tm * 8 + i;
        float4 o0 = make_float4(acc[i][0]+bv[0], acc[i][1]+bv[1], acc[i][2]+bv[2], acc[i][3]+bv[3]);
        float4 o1 = make_float4(acc[i][4]+bv[4], acc[i][5]+bv[5], acc[i][6]+bv[6], acc[i][7]+bv[7]);
        *(float4*)(C + (size_t)m * N + n0 + tn * 8)     = o0;
        *(float4*)(C + (size_t)m * N + n0 + tn * 8 + 4) = o1;
    }
}

// ===========================================================================
// Reset kernel: zero inter-CTA barrier counters (stream-ordered before rnn)
// ===========================================================================
__global__ void reset_k()
{
    if (threadIdx.x < 4) g_arrive[threadIdx.x] = 0u;
}

// ===========================================================================
// Persistent LSTM recurrence.
// grid = 128 CTAs x 256 threads. CTA c: pair = c>>5 (batches 2p, 2p+1),
// grp = c&31 (hidden units [grp*16, grp*16+16)). Each CTA keeps its 64
// W_hh rows (4 gates x 16 units) x its k-quarter in registers for all steps.
// Barrier per step across the 32 CTAs of a batch pair (monotone counter).
// ===========================================================================
__device__ __forceinline__ float sigm(float x) { return 1.f / (1.f + expf(-x)); }

__global__ void __launch_bounds__(256, 1) rnn_kernel(
    const float* __restrict__ W_hh, const float* __restrict__ h0,
    const float* __restrict__ c0)
{
    const int cta  = blockIdx.x;
    const int pair = cta >> 5;          // 0..3
    const int grp  = cta & 31;          // 0..31
    const int tid  = threadIdx.x;
    const int q    = tid >> 6;          // k-quarter 0..3
    const int r    = tid & 63;          // gate-row 0..63
    const int gate = r >> 4, uu = r & 15;
    const int unit = grp * 16 + uu;

    __shared__ float h_sm[2][H_];
    __shared__ float red[4][64][2];
    __shared__ float gsm[64][2];
    __shared__ float c_sm[2][16];

    // register-resident W_hh slice: row (gate*512+unit), cols [q*128, q*128+128)
    float w[128];
    {
        const float4* wp = (const float4*)(W_hh + (size_t)(gate * H_ + unit) * H_ + q * 128);
#pragma unroll
        for (int j = 0; j < 32; j++) {
            float4 v = wp[j];
            w[4*j+0] = v.x; w[4*j+1] = v.y; w[4*j+2] = v.z; w[4*j+3] = v.w;
        }
    }

    for (int s = 0; s < S_; s++) {
        // load h (both batches of this pair) into smem; bypass L1 (peer writes)
        {
            const int bb = tid >> 7, off = (tid & 127) * 4;
            float4 v;
            if (s == 0) v = *(const float4*)(h0 + (size_t)(pair*2 + bb) * H_ + off);
            else        v = __ldcg((const float4*)(g_hcur + (size_t)(pair*2 + bb) * H_ + off));
            *(float4*)&h_sm[bb][off] = v;
        }
        if (s == 0 && tid < 32) {
            int b2 = tid >> 4, u2 = tid & 15;
            c_sm[b2][u2] = c0[(size_t)(pair*2 + b2) * H_ + grp*16 + u2];
        }
        __syncthreads();

        float a0 = 0.f, a1 = 0.f;
        {
            const float* hp0 = &h_sm[0][q * 128];
            const float* hp1 = &h_sm[1][q * 128];
#pragma unroll
            for (int j = 0; j < 128; j++) {
                a0 += w[j] * hp0[j];
                a1 += w[j] * hp1[j];
            }
        }
        red[q][r][0] = a0;
        red[q][r][1] = a1;
        __syncthreads();

        if (tid < 128) {
            const int rr = tid >> 1, bb = tid & 1;
            const int gg = rr >> 4, u2 = rr & 15;
            float g = red[0][rr][bb] + red[1][rr][bb] + red[2][rr][bb] + red[3][rr][bb]
                    + g_xg[((size_t)(pair*2 + bb) * S_ + s) * G4_ + gg * H_ + grp*16 + u2];
            gsm[rr][bb] = g;
        }
        __syncthreads();

        if (tid < 32) {
            const int bb = tid >> 4, u2 = tid & 15;
            float iv = gsm[ 0 + u2][bb];
            float fv = gsm[16 + u2][bb];
            float gv = gsm[32 + u2][bb];
            float ov = gsm[48 + u2][bb];
            float cn = sigm(fv) * c_sm[bb][u2] + sigm(iv) * tanhf(gv);
            float hn = sigm(ov) * tanhf(cn);
            c_sm[bb][u2] = cn;
            const int bg = pair*2 + bb, un = grp*16 + u2;
            g_hcur[(size_t)bg * H_ + un] = hn;
            g_H[((size_t)bg * S_ + s) * H_ + un] = hn;
            __threadfence();
        }
        __syncthreads();

        // ---- barrier across the 32 CTAs of this batch pair ----
        if (tid == 0) {
            atomicAdd(&g_arrive[pair], 1u);
            const unsigned target = 32u * (unsigned)(s + 1);
            while (*((volatile unsigned*)&g_arrive[pair]) < target) { }
        }
        __syncthreads();
        __threadfence();
    }
}

// ===========================================================================
// Attention scores: scores[bh][s][k] = (q . k) * scale, masked.
// grid (SKV/64=16, S/64=4, B*NH=64), 256 threads, 64x64 tile, d=64 inner.
// ===========================================================================
__global__ void __launch_bounds__(256) attn_scores_k(const int* __restrict__ mask)
{
    __shared__ float Qs[64][65];
    __shared__ float Ks[64][65];
    const int bh = blockIdx.z, b = bh >> 3, h = bh & 7;
    const int s0 = blockIdx.y * 64, k0 = blockIdx.x * 64;
    const int tid = threadIdx.x;

    for (int e = tid; e < 64 * 64; e += 256) {
        int row = e >> 6, col = e & 63;
        Qs[row][col] = g_Q[((size_t)b * S_ + s0 + row) * H_ + h * HD_ + col];
        Ks[row][col] = g_K[((size_t)b * SKV_ + k0 + row) * H_ + h * HD_ + col];
    }
    __syncthreads();

    const int tm = tid >> 4, tn = tid & 15;
    float acc[4][4];
#pragma unroll
    for (int i = 0; i < 4; i++)
#pragma unroll
        for (int j = 0; j < 4; j++) acc[i][j] = 0.f;

#pragma unroll 8
    for (int d = 0; d < 64; d++) {
        float a[4], bb[4];
#pragma unroll
        for (int i = 0; i < 4; i++) a[i]  = Qs[tm*4 + i][d];
#pragma unroll
        for (int j = 0; j < 4; j++) bb[j] = Ks[tn*4 + j][d];
#pragma unroll
        for (int i = 0; i < 4; i++)
#pragma unroll
            for (int j = 0; j < 4; j++) acc[i][j] += a[i] * bb[j];
    }

    const float scale = 0.125f;  // 1/sqrt(64)
#pragma unroll
    for (int i = 0; i < 4; i++) {
        int s = s0 + tm*4 + i;
#pragma unroll
        for (int j = 0; j < 4; j++) {
            int k = k0 + tn*4 + j;
            float v = acc[i][j] * scale;
            if (mask[b * SKV_ + k] != 1) v = -1e9f;
            g_att[((size_t)bh * S_ + s) * SKV_ + k] = v;
        }
    }
}

// ===========================================================================
// Softmax over last dim (SKV=1024). grid = B*NH*S = 16384 blocks, 128 thr.
// ===========================================================================
__global__ void __launch_bounds__(128) softmax_k()
{
    const size_t base = (size_t)blockIdx.x * SKV_;
    const int tid = threadIdx.x;
    float v[8];
    float mx = -1e30f;
#pragma unroll
    for (int i = 0; i < 8; i++) {
        v[i] = g_att[base + tid + i * 128];
        mx = fmaxf(mx, v[i]);
    }
    __shared__ float sm[4];
#pragma unroll
    for (int off = 16; off > 0; off >>= 1)
        mx = fmaxf(mx, __shfl_xor_sync(0xffffffffu, mx, off));
    if ((tid & 31) == 0) sm[tid >> 5] = mx;
    __syncthreads();
    mx = fmaxf(fmaxf(sm[0], sm[1]), fmaxf(sm[2], sm[3]));

    float sum = 0.f;
#pragma unroll
    for (int i = 0; i < 8; i++) { v[i] = expf(v[i] - mx); sum += v[i]; }
#pragma unroll
    for (int off = 16; off > 0; off >>= 1)
        sum += __shfl_xor_sync(0xffffffffu, sum, off);
    __syncthreads();
    if ((tid & 31) == 0) sm[tid >> 5] = sum;
    __syncthreads();
    sum = sm[0] + sm[1] + sm[2] + sm[3];
    const float inv = 1.f / sum;
#pragma unroll
    for (int i = 0; i < 8; i++) g_att[base + tid + i * 128] = v[i] * inv;
}

// ===========================================================================
// ctx[bt][h*64+d] = sum_k attn[bh][s][k] * V[b][k][h*64+d]
// grid (S/64=4, B*NH=64), 256 threads, 64 queries x 64 d, k tiles of 64.
// ===========================================================================
__global__ void __launch_bounds__(256) attn_ctx_k()
{
    __shared__ float As[64][65];
    __shared__ float Vs[64][65];
    const int bh = blockIdx.y, b = bh >> 3, h = bh & 7;
    const int s0 = blockIdx.x * 64;
    const int tid = threadIdx.x;
    const int tm = tid >> 4, tn = tid & 15;

    float acc[4][4];
#pragma unroll
    for (int i = 0; i < 4; i++)
#pragma unroll
        for (int j = 0; j < 4; j++) acc[i][j] = 0.f;

    for (int kt = 0; kt < SKV_; kt += 64) {
        for (int e = tid; e < 64 * 64; e += 256) {
            int row = e >> 6, col = e & 63;
            As[row][col] = g_att[((size_t)bh * S_ + s0 + row) * SKV_ + kt + col];
            Vs[row][col] = g_V[((size_t)b * SKV_ + kt + row) * H_ + h * HD_ + col];
        }
        __syncthreads();
#pragma unroll 8
        for (int kk = 0; kk < 64; kk++) {
            float a[4], vv[4];
#pragma unroll
            for (int i = 0; i < 4; i++) a[i]  = As[tm*4 + i][kk];
#pragma unroll
            for (int j = 0; j < 4; j++) vv[j] = Vs[kk][tn*4 + j];
#pragma unroll
            for (int i = 0; i < 4; i++)
#pragma unroll
                for (int j = 0; j < 4; j++) acc[i][j] += a[i] * vv[j];
        }
        __syncthreads();
    }

#pragma unroll
    for (int i = 0; i < 4; i++) {
        int s = s0 + tm*4 + i;
#pragma unroll
        for (int j = 0; j < 4; j++)
            g_ctx[((size_t)b * S_ + s) * H_ + h * HD_ + tn*4 + j] = acc[i][j];
    }
}

// ===========================================================================
// Host orchestration
// ===========================================================================
extern "C" void kernel_launch(void* const* d_in, const int* in_sizes, int n_in,
                              void* d_out, int out_size)
{
    const int*   tok   = (const int*)  d_in[0];
    const float* enc   = (const float*)d_in[1];
    const int*   mask  = (const int*)  d_in[2];
    const float* emb   = (const float*)d_in[3];
    const float* W_ih  = (const float*)d_in[4];
    const float* W_hh  = (const float*)d_in[5];
    const float* b_ih  = (const float*)d_in[6];
    const float* b_hh  = (const float*)d_in[7];
    const float* Wq    = (const float*)d_in[8];
    const float* bq    = (const float*)d_in[9];
    const float* Wk    = (const float*)d_in[10];
    const float* bk    = (const float*)d_in[11];
    const float* Wv    = (const float*)d_in[12];
    const float* bv    = (const float*)d_in[13];
    const float* Wo    = (const float*)d_in[14];
    const float* bo    = (const float*)d_in[15];
    const float* h0    = (const float*)d_in[16];
    const float* c0    = (const float*)d_in[17];
    float* out = (float*)d_out;

    float *p_xg, *p_K, *p_V, *p_H, *p_Q, *p_ctx, *p_outs;
    cudaGetSymbolAddress((void**)&p_xg,   g_xg);
    cudaGetSymbolAddress((void**)&p_K,    g_K);
    cudaGetSymbolAddress((void**)&p_V,    g_V);
    cudaGetSymbolAddress((void**)&p_H,    g_H);
    cudaGetSymbolAddress((void**)&p_Q,    g_Q);
    cudaGetSymbolAddress((void**)&p_ctx,  g_ctx);
    cudaGetSymbolAddress((void**)&p_outs, g_outs);

    // barrier counters must be zero before the persistent recurrence
    reset_k<<<1, 32>>>();

    // x-gates with fused embedding gather: [2048,2048] = gather(emb) @ W_ih^T + b_ih + b_hh
    sgemm_tn<<<dim3(G4_/128, BT_/128), 256>>>(BT_, G4_, H_, emb, tok, W_ih, b_ih, b_hh, p_xg);
    // encoder K/V projections: [8192,512]
    sgemm_tn<<<dim3(H_/128, BKV_/128), 256>>>(BKV_, H_, H_, enc, nullptr, Wk, bk, nullptr, p_K);
    sgemm_tn<<<dim3(H_/128, BKV_/128), 256>>>(BKV_, H_, H_, enc, nullptr, Wv, bv, nullptr, p_V);

    // serial LSTM recurrence -> g_H (hidden history), consumes g_xg
    rnn_kernel<<<128, 256>>>(W_hh, h0, c0);

    // Q projection from hidden history
    sgemm_tn<<<dim3(H_/128, BT_/128), 256>>>(BT_, H_, H_, p_H, nullptr, Wq, bq, nullptr, p_Q);

    // attention
    attn_scores_k<<<dim3(SKV_/64, S_/64, B_*NH_), 256>>>(mask);
    softmax_k<<<B_*NH_*S_, 128>>>();
    attn_ctx_k<<<dim3(S_/64, B_*NH_), 256>>>();

    // output projection
    sgemm_tn<<<dim3(H_/128, BT_/128), 256>>>(BT_, H_, H_, p_ctx, nullptr, Wo, bo, nullptr, p_outs);

    // tied logits: [2048, 32000] = outs @ emb^T
    sgemm_tn<<<dim3(V_/128, BT_/128), 256>>>(BT_, V_, H_, p_outs, nullptr, emb, nullptr, nullptr, out);
}

// round 5
// speedup vs baseline: 1.1701x; 1.1701x over previous
#include <cuda_runtime.h>
#include <cuda_bf16.h>
#include <math.h>

// ---------------- problem constants ----------------
#define B_    8
#define S_    256
#define SKV_  1024
#define H_    512
#define NH_   8
#define HD_   64
#define G4_   2048            // 4*H
#define V_    32000
#define BT_   (B_*S_)         // 2048
#define BKV_  (B_*SKV_)       // 8192

// ---------------- device scratch (static; allocation is forbidden) --------
__device__ float    g_xg  [BT_  * (size_t)G4_];   // x@W_ih^T + b_ih + b_hh
__device__ float    g_K   [BKV_ * (size_t)H_];
__device__ float    g_V   [BKV_ * (size_t)H_];
__device__ float    g_H   [BT_  * (size_t)H_];    // hidden history
__device__ float    g_Q   [BT_  * (size_t)H_];
__device__ float    g_ctx [BT_  * (size_t)H_];
__device__ float    g_outs[BT_  * (size_t)H_];
__device__ float    g_hcur[B_ * H_];
__device__ float    g_att [(size_t)B_ * NH_ * S_ * SKV_];  // 67 MB
__device__ unsigned g_arrive[4];
// split-bf16 buffers for the tensor-core logits GEMM
__device__ __nv_bfloat16 g_embhi[(size_t)V_ * H_];
__device__ __nv_bfloat16 g_emblo[(size_t)V_ * H_];
__device__ __nv_bfloat16 g_outhi[(size_t)BT_ * H_];
__device__ __nv_bfloat16 g_outlo[(size_t)BT_ * H_];

// ===========================================================================
// Generic fp32 SGEMM:  C[m][n] = sum_k A'[m][k]*Bm[n][k] (+bias1[n]+bias2[n])
// A'[m] = A[gidx[m]] when gidx != nullptr (embedding gather).
// ===========================================================================
__global__ void __launch_bounds__(256) sgemm_tn(
    int M, int N, int K,
    const float* __restrict__ A, const int* __restrict__ gidx,
    const float* __restrict__ Bm,
    const float* __restrict__ bias1, const float* __restrict__ bias2,
    float* __restrict__ C)
{
    __shared__ float As[16][132];
    __shared__ float Bs[16][132];
    const int tid = threadIdx.x;
    const int m0 = blockIdx.y * 128, n0 = blockIdx.x * 128;
    const int tm = tid >> 4, tn = tid & 15;

    float acc[8][8];
#pragma unroll
    for (int i = 0; i < 8; i++)
#pragma unroll
        for (int j = 0; j < 8; j++) acc[i][j] = 0.f;

    const int id0 = tid * 2, id1 = tid * 2 + 1;
    const int r0 = id0 >> 2, k0 = (id0 & 3) * 4;
    const int r1 = id1 >> 2, k1 = (id1 & 3) * 4;
    int am0 = m0 + r0; if (gidx) am0 = gidx[am0];
    int am1 = m0 + r1; if (gidx) am1 = gidx[am1];
    const float* Arow0 = A  + (size_t)am0 * K;
    const float* Arow1 = A  + (size_t)am1 * K;
    const float* Brow0 = Bm + (size_t)(n0 + r0) * K;
    const float* Brow1 = Bm + (size_t)(n0 + r1) * K;

    for (int kt = 0; kt < K; kt += 16) {
        float4 a0 = *(const float4*)(Arow0 + kt + k0);
        float4 a1 = *(const float4*)(Arow1 + kt + k1);
        float4 b0 = *(const float4*)(Brow0 + kt + k0);
        float4 b1 = *(const float4*)(Brow1 + kt + k1);
        __syncthreads();
        As[k0+0][r0] = a0.x; As[k0+1][r0] = a0.y; As[k0+2][r0] = a0.z; As[k0+3][r0] = a0.w;
        As[k1+0][r1] = a1.x; As[k1+1][r1] = a1.y; As[k1+2][r1] = a1.z; As[k1+3][r1] = a1.w;
        Bs[k0+0][r0] = b0.x; Bs[k0+1][r0] = b0.y; Bs[k0+2][r0] = b0.z; Bs[k0+3][r0] = b0.w;
        Bs[k1+0][r1] = b1.x; Bs[k1+1][r1] = b1.y; Bs[k1+2][r1] = b1.z; Bs[k1+3][r1] = b1.w;
        __syncthreads();
#pragma unroll
        for (int kk = 0; kk < 16; kk++) {
            const float4* Ap = (const float4*)&As[kk][tm * 8];
            const float4* Bp = (const float4*)&Bs[kk][tn * 8];
            float4 av0 = Ap[0], av1 = Ap[1];
            float4 bv0 = Bp[0], bv1 = Bp[1];
            float a[8] = {av0.x,av0.y,av0.z,av0.w, av1.x,av1.y,av1.z,av1.w};
            float b[8] = {bv0.x,bv0.y,bv0.z,bv0.w, bv1.x,bv1.y,bv1.z,bv1.w};
#pragma unroll
            for (int i = 0; i < 8; i++)
#pragma unroll
                for (int j = 0; j < 8; j++) acc[i][j] += a[i] * b[j];
        }
    }

    float bv[8];
#pragma unroll
    for (int j = 0; j < 8; j++) {
        int n = n0 + tn * 8 + j;
        float t = 0.f;
        if (bias1) t += bias1[n];
        if (bias2) t += bias2[n];
        bv[j] = t;
    }
#pragma unroll
    for (int i = 0; i < 8; i++) {
        int m = m0 + tm * 8 + i;
        float4 o0 = make_float4(acc[i][0]+bv[0], acc[i][1]+bv[1], acc[i][2]+bv[2], acc[i][3]+bv[3]);
        float4 o1 = make_float4(acc[i][4]+bv[4], acc[i][5]+bv[5], acc[i][6]+bv[6], acc[i][7]+bv[7]);
        *(float4*)(C + (size_t)m * N + n0 + tn * 8)     = o0;
        *(float4*)(C + (size_t)m * N + n0 + tn * 8 + 4) = o1;
    }
}

// ===========================================================================
// fp32 -> (bf16 hi, bf16 lo) split, vectorized by 4
// ===========================================================================
__global__ void __launch_bounds__(256) split_bf16_k(
    const float* __restrict__ x, __nv_bfloat16* __restrict__ hi,
    __nv_bfloat16* __restrict__ lo, int n4)
{
    int i = blockIdx.x * 256 + threadIdx.x;
    if (i >= n4) return;
    float4 v = ((const float4*)x)[i];
    __nv_bfloat16 h0 = __float2bfloat16(v.x), h1 = __float2bfloat16(v.y);
    __nv_bfloat16 h2 = __float2bfloat16(v.z), h3 = __float2bfloat16(v.w);
    __nv_bfloat16 l0 = __float2bfloat16(v.x - __bfloat162float(h0));
    __nv_bfloat16 l1 = __float2bfloat16(v.y - __bfloat162float(h1));
    __nv_bfloat16 l2 = __float2bfloat16(v.z - __bfloat162float(h2));
    __nv_bfloat16 l3 = __float2bfloat16(v.w - __bfloat162float(h3));
    __nv_bfloat162* hp = (__nv_bfloat162*)(hi + (size_t)i * 4);
    __nv_bfloat162* lp = (__nv_bfloat162*)(lo + (size_t)i * 4);
    hp[0] = __nv_bfloat162(h0, h1); hp[1] = __nv_bfloat162(h2, h3);
    lp[0] = __nv_bfloat162(l0, l1); lp[1] = __nv_bfloat162(l2, l3);
}

// ===========================================================================
// Tensor-core logits GEMM: C[2048][32000] = outs @ emb^T in split-bf16.
// 3 K-segments: (Ahi,Bhi), (Ahi,Blo), (Alo,Bhi); K=512 each -> 48 BK=32 iters.
// 256 thr, CTA tile 128x128, 8 warps (4m x 2n), warp tile 32x64,
// mma.sync.m16n8k16 bf16 with fp32 accumulators.
// grid = (M/128=16, N/128=250); x (m) fastest for emb-tile L2 reuse.
// ===========================================================================
__global__ void __launch_bounds__(256, 2) gemm_logits_bf16(
    const __nv_bfloat16* __restrict__ Ahi, const __nv_bfloat16* __restrict__ Alo,
    const __nv_bfloat16* __restrict__ Bhi, const __nv_bfloat16* __restrict__ Blo,
    float* __restrict__ C)
{
    __shared__ __nv_bfloat16 As[128][40];   // pad 8 halves -> conflict-free
    __shared__ __nv_bfloat16 Bs[128][40];

    const int tid  = threadIdx.x;
    const int m0   = blockIdx.x * 128;
    const int n0   = blockIdx.y * 128;
    const int warp = tid >> 5, lane = tid & 31;
    const int wm   = warp >> 1, wn = warp & 1;
    const int g    = lane >> 2, t4 = lane & 3;

    float acc[2][8][4];
#pragma unroll
    for (int mi = 0; mi < 2; mi++)
#pragma unroll
        for (int ni = 0; ni < 8; ni++)
#pragma unroll
            for (int f = 0; f < 4; f++) acc[mi][ni][f] = 0.f;

    const int lr = tid >> 1;            // tile row this thread loads
    const int lc = (tid & 1) * 16;      // half-col base (0 or 16)

    uint4 ra0, ra1, rb0, rb1;
    {   // prefetch iter 0: seg 0 -> Ahi, Bhi, kofs 0
        const __nv_bfloat16* ap = Ahi + (size_t)(m0 + lr) * H_ + lc;
        const __nv_bfloat16* bp = Bhi + (size_t)(n0 + lr) * H_ + lc;
        ra0 = *(const uint4*)ap; ra1 = *(const uint4*)(ap + 8);
        rb0 = *(const uint4*)bp; rb1 = *(const uint4*)(bp + 8);
    }

    for (int it = 0; it < 48; it++) {
        __syncthreads();
        *(uint4*)&As[lr][lc]     = ra0;
        *(uint4*)&As[lr][lc + 8] = ra1;
        *(uint4*)&Bs[lr][lc]     = rb0;
        *(uint4*)&Bs[lr][lc + 8] = rb1;
        __syncthreads();

        if (it + 1 < 48) {
            int nit  = it + 1;
            int seg  = nit >> 4;
            int kofs = (nit & 15) * 32;
            const __nv_bfloat16* Ap = (seg < 2) ? Ahi : Alo;
            const __nv_bfloat16* Bp = (seg == 1) ? Blo : Bhi;
            const __nv_bfloat16* ap = Ap + (size_t)(m0 + lr) * H_ + kofs + lc;
            const __nv_bfloat16* bp = Bp + (size_t)(n0 + lr) * H_ + kofs + lc;
            ra0 = *(const uint4*)ap; ra1 = *(const uint4*)(ap + 8);
            rb0 = *(const uint4*)bp; rb1 = *(const uint4*)(bp + 8);
        }

#pragma unroll
        for (int k0 = 0; k0 < 32; k0 += 16) {
            unsigned a[2][4];
#pragma unroll
            for (int mi = 0; mi < 2; mi++) {
                const int am = wm * 32 + mi * 16;
                a[mi][0] = *(const unsigned*)&As[am + g    ][k0 + 2 * t4];
                a[mi][1] = *(const unsigned*)&As[am + g + 8][k0 + 2 * t4];
                a[mi][2] = *(const unsigned*)&As[am + g    ][k0 + 8 + 2 * t4];
                a[mi][3] = *(const unsigned*)&As[am + g + 8][k0 + 8 + 2 * t4];
            }
#pragma unroll
            for (int ni = 0; ni < 8; ni++) {
                const int bn = wn * 64 + ni * 8;
                unsigned b0 = *(const unsigned*)&Bs[bn + g][k0 + 2 * t4];
                unsigned b1 = *(const unsigned*)&Bs[bn + g][k0 + 8 + 2 * t4];
#pragma unroll
                for (int mi = 0; mi < 2; mi++) {
                    asm volatile(
                        "mma.sync.aligned.m16n8k16.row.col.f32.bf16.bf16.f32 "
                        "{%0,%1,%2,%3}, {%4,%5,%6,%7}, {%8,%9}, {%0,%1,%2,%3};\n"
                        : "+f"(acc[mi][ni][0]), "+f"(acc[mi][ni][1]),
                          "+f"(acc[mi][ni][2]), "+f"(acc[mi][ni][3])
                        : "r"(a[mi][0]), "r"(a[mi][1]), "r"(a[mi][2]), "r"(a[mi][3]),
                          "r"(b0), "r"(b1));
                }
            }
        }
    }

#pragma unroll
    for (int mi = 0; mi < 2; mi++) {
#pragma unroll
        for (int ni = 0; ni < 8; ni++) {
            int row = m0 + wm * 32 + mi * 16 + g;
            int col = n0 + wn * 64 + ni * 8 + 2 * t4;
            float2 v0 = make_float2(acc[mi][ni][0], acc[mi][ni][1]);
            float2 v1 = make_float2(acc[mi][ni][2], acc[mi][ni][3]);
            *(float2*)&C[(size_t)row * V_ + col]       = v0;
            *(float2*)&C[(size_t)(row + 8) * V_ + col] = v1;
        }
    }
}

// ===========================================================================
// Reset kernel: zero inter-CTA barrier counters
// ===========================================================================
__global__ void reset_k()
{
    if (threadIdx.x < 4) g_arrive[threadIdx.x] = 0u;
}

// ===========================================================================
// Persistent LSTM recurrence (unchanged from passing R3 kernel)
// ===========================================================================
__device__ __forceinline__ float sigm(float x) { return 1.f / (1.f + expf(-x)); }

__global__ void __launch_bounds__(256, 1) rnn_kernel(
    const float* __restrict__ W_hh, const float* __restrict__ h0,
    const float* __restrict__ c0)
{
    const int cta  = blockIdx.x;
    const int pair = cta >> 5;
    const int grp  = cta & 31;
    const int tid  = threadIdx.x;
    const int q    = tid >> 6;
    const int r    = tid & 63;
    const int gate = r >> 4, uu = r & 15;
    const int unit = grp * 16 + uu;

    __shared__ float h_sm[2][H_];
    __shared__ float red[4][64][2];
    __shared__ float gsm[64][2];
    __shared__ float c_sm[2][16];

    float w[128];
    {
        const float4* wp = (const float4*)(W_hh + (size_t)(gate * H_ + unit) * H_ + q * 128);
#pragma unroll
        for (int j = 0; j < 32; j++) {
            float4 v = wp[j];
            w[4*j+0] = v.x; w[4*j+1] = v.y; w[4*j+2] = v.z; w[4*j+3] = v.w;
        }
    }

    for (int s = 0; s < S_; s++) {
        {
            const int bb = tid >> 7, off = (tid & 127) * 4;
            float4 v;
            if (s == 0) v = *(const float4*)(h0 + (size_t)(pair*2 + bb) * H_ + off);
            else        v = __ldcg((const float4*)(g_hcur + (size_t)(pair*2 + bb) * H_ + off));
            *(float4*)&h_sm[bb][off] = v;
        }
        if (s == 0 && tid < 32) {
            int b2 = tid >> 4, u2 = tid & 15;
            c_sm[b2][u2] = c0[(size_t)(pair*2 + b2) * H_ + grp*16 + u2];
        }
        __syncthreads();

        float a0 = 0.f, a1 = 0.f;
        {
            const float* hp0 = &h_sm[0][q * 128];
            const float* hp1 = &h_sm[1][q * 128];
#pragma unroll
            for (int j = 0; j < 128; j++) {
                a0 += w[j] * hp0[j];
                a1 += w[j] * hp1[j];
            }
        }
        red[q][r][0] = a0;
        red[q][r][1] = a1;
        __syncthreads();

        if (tid < 128) {
            const int rr = tid >> 1, bb = tid & 1;
            const int gg = rr >> 4, u2 = rr & 15;
            float g = red[0][rr][bb] + red[1][rr][bb] + red[2][rr][bb] + red[3][rr][bb]
                    + g_xg[((size_t)(pair*2 + bb) * S_ + s) * G4_ + gg * H_ + grp*16 + u2];
            gsm[rr][bb] = g;
        }
        __syncthreads();

        if (tid < 32) {
            const int bb = tid >> 4, u2 = tid & 15;
            float iv = gsm[ 0 + u2][bb];
            float fv = gsm[16 + u2][bb];
            float gv = gsm[32 + u2][bb];
            float ov = gsm[48 + u2][bb];
            float cn = sigm(fv) * c_sm[bb][u2] + sigm(iv) * tanhf(gv);
            float hn = sigm(ov) * tanhf(cn);
            c_sm[bb][u2] = cn;
            const int bg = pair*2 + bb, un = grp*16 + u2;
            g_hcur[(size_t)bg * H_ + un] = hn;
            g_H[((size_t)bg * S_ + s) * H_ + un] = hn;
            __threadfence();
        }
        __syncthreads();

        if (tid == 0) {
            atomicAdd(&g_arrive[pair], 1u);
            const unsigned target = 32u * (unsigned)(s + 1);
            while (*((volatile unsigned*)&g_arrive[pair]) < target) { }
        }
        __syncthreads();
        __threadfence();
    }
}

// ===========================================================================
// Attention scores
// ===========================================================================
__global__ void __launch_bounds__(256) attn_scores_k(const int* __restrict__ mask)
{
    __shared__ float Qs[64][65];
    __shared__ float Ks[64][65];
    const int bh = blockIdx.z, b = bh >> 3, h = bh & 7;
    const int s0 = blockIdx.y * 64, k0 = blockIdx.x * 64;
    const int tid = threadIdx.x;

    for (int e = tid; e < 64 * 64; e += 256) {
        int row = e >> 6, col = e & 63;
        Qs[row][col] = g_Q[((size_t)b * S_ + s0 + row) * H_ + h * HD_ + col];
        Ks[row][col] = g_K[((size_t)b * SKV_ + k0 + row) * H_ + h * HD_ + col];
    }
    __syncthreads();

    const int tm = tid >> 4, tn = tid & 15;
    float acc[4][4];
#pragma unroll
    for (int i = 0; i < 4; i++)
#pragma unroll
        for (int j = 0; j < 4; j++) acc[i][j] = 0.f;

#pragma unroll 8
    for (int d = 0; d < 64; d++) {
        float a[4], bb[4];
#pragma unroll
        for (int i = 0; i < 4; i++) a[i]  = Qs[tm*4 + i][d];
#pragma unroll
        for (int j = 0; j < 4; j++) bb[j] = Ks[tn*4 + j][d];
#pragma unroll
        for (int i = 0; i < 4; i++)
#pragma unroll
            for (int j = 0; j < 4; j++) acc[i][j] += a[i] * bb[j];
    }

    const float scale = 0.125f;
#pragma unroll
    for (int i = 0; i < 4; i++) {
        int s = s0 + tm*4 + i;
#pragma unroll
        for (int j = 0; j < 4; j++) {
            int k = k0 + tn*4 + j;
            float v = acc[i][j] * scale;
            if (mask[b * SKV_ + k] != 1) v = -1e9f;
            g_att[((size_t)bh * S_ + s) * SKV_ + k] = v;
        }
    }
}

// ===========================================================================
// Softmax over SKV=1024
// ===========================================================================
__global__ void __launch_bounds__(128) softmax_k()
{
    const size_t base = (size_t)blockIdx.x * SKV_;
    const int tid = threadIdx.x;
    float v[8];
    float mx = -1e30f;
#pragma unroll
    for (int i = 0; i < 8; i++) {
        v[i] = g_att[base + tid + i * 128];
        mx = fmaxf(mx, v[i]);
    }
    __shared__ float sm[4];
#pragma unroll
    for (int off = 16; off > 0; off >>= 1)
        mx = fmaxf(mx, __shfl_xor_sync(0xffffffffu, mx, off));
    if ((tid & 31) == 0) sm[tid >> 5] = mx;
    __syncthreads();
    mx = fmaxf(fmaxf(sm[0], sm[1]), fmaxf(sm[2], sm[3]));

    float sum = 0.f;
#pragma unroll
    for (int i = 0; i < 8; i++) { v[i] = expf(v[i] - mx); sum += v[i]; }
#pragma unroll
    for (int off = 16; off > 0; off >>= 1)
        sum += __shfl_xor_sync(0xffffffffu, sum, off);
    __syncthreads();
    if ((tid & 31) == 0) sm[tid >> 5] = sum;
    __syncthreads();
    sum = sm[0] + sm[1] + sm[2] + sm[3];
    const float inv = 1.f / sum;
#pragma unroll
    for (int i = 0; i < 8; i++) g_att[base + tid + i * 128] = v[i] * inv;
}

// ===========================================================================
// attn @ V
// ===========================================================================
__global__ void __launch_bounds__(256) attn_ctx_k()
{
    __shared__ float As[64][65];
    __shared__ float Vs[64][65];
    const int bh = blockIdx.y, b = bh >> 3, h = bh & 7;
    const int s0 = blockIdx.x * 64;
    const int tid = threadIdx.x;
    const int tm = tid >> 4, tn = tid & 15;

    float acc[4][4];
#pragma unroll
    for (int i = 0; i < 4; i++)
#pragma unroll
        for (int j = 0; j < 4; j++) acc[i][j] = 0.f;

    for (int kt = 0; kt < SKV_; kt += 64) {
        for (int e = tid; e < 64 * 64; e += 256) {
            int row = e >> 6, col = e & 63;
            As[row][col] = g_att[((size_t)bh * S_ + s0 + row) * SKV_ + kt + col];
            Vs[row][col] = g_V[((size_t)b * SKV_ + kt + row) * H_ + h * HD_ + col];
        }
        __syncthreads();
#pragma unroll 8
        for (int kk = 0; kk < 64; kk++) {
            float a[4], vv[4];
#pragma unroll
            for (int i = 0; i < 4; i++) a[i]  = As[tm*4 + i][kk];
#pragma unroll
            for (int j = 0; j < 4; j++) vv[j] = Vs[kk][tn*4 + j];
#pragma unroll
            for (int i = 0; i < 4; i++)
#pragma unroll
                for (int j = 0; j < 4; j++) acc[i][j] += a[i] * vv[j];
        }
        __syncthreads();
    }

#pragma unroll
    for (int i = 0; i < 4; i++) {
        int s = s0 + tm*4 + i;
#pragma unroll
        for (int j = 0; j < 4; j++)
            g_ctx[((size_t)b * S_ + s) * H_ + h * HD_ + tn*4 + j] = acc[i][j];
    }
}

// ===========================================================================
// Host orchestration
// ===========================================================================
extern "C" void kernel_launch(void* const* d_in, const int* in_sizes, int n_in,
                              void* d_out, int out_size)
{
    const int*   tok   = (const int*)  d_in[0];
    const float* enc   = (const float*)d_in[1];
    const int*   mask  = (const int*)  d_in[2];
    const float* emb   = (const float*)d_in[3];
    const float* W_ih  = (const float*)d_in[4];
    const float* W_hh  = (const float*)d_in[5];
    const float* b_ih  = (const float*)d_in[6];
    const float* b_hh  = (const float*)d_in[7];
    const float* Wq    = (const float*)d_in[8];
    const float* bq    = (const float*)d_in[9];
    const float* Wk    = (const float*)d_in[10];
    const float* bk    = (const float*)d_in[11];
    const float* Wv    = (const float*)d_in[12];
    const float* bv    = (const float*)d_in[13];
    const float* Wo    = (const float*)d_in[14];
    const float* bo    = (const float*)d_in[15];
    const float* h0    = (const float*)d_in[16];
    const float* c0    = (const float*)d_in[17];
    float* out = (float*)d_out;

    float *p_xg, *p_K, *p_V, *p_H, *p_Q, *p_ctx, *p_outs;
    __nv_bfloat16 *p_ehi, *p_elo, *p_ohi, *p_olo;
    cudaGetSymbolAddress((void**)&p_xg,   g_xg);
    cudaGetSymbolAddress((void**)&p_K,    g_K);
    cudaGetSymbolAddress((void**)&p_V,    g_V);
    cudaGetSymbolAddress((void**)&p_H,    g_H);
    cudaGetSymbolAddress((void**)&p_Q,    g_Q);
    cudaGetSymbolAddress((void**)&p_ctx,  g_ctx);
    cudaGetSymbolAddress((void**)&p_outs, g_outs);
    cudaGetSymbolAddress((void**)&p_ehi,  g_embhi);
    cudaGetSymbolAddress((void**)&p_elo,  g_emblo);
    cudaGetSymbolAddress((void**)&p_ohi,  g_outhi);
    cudaGetSymbolAddress((void**)&p_olo,  g_outlo);

    // barrier counters must be zero before the persistent recurrence
    reset_k<<<1, 32>>>();

    // split emb into bf16 hi/lo for the tensor-core logits GEMM (independent)
    {
        int n4 = (V_ * H_) / 4;                 // 4.096M float4s
        split_bf16_k<<<(n4 + 255) / 256, 256>>>(emb, p_ehi, p_elo, n4);
    }

    // x-gates with fused embedding gather
    sgemm_tn<<<dim3(G4_/128, BT_/128), 256>>>(BT_, G4_, H_, emb, tok, W_ih, b_ih, b_hh, p_xg);
    // encoder K/V projections
    sgemm_tn<<<dim3(H_/128, BKV_/128), 256>>>(BKV_, H_, H_, enc, nullptr, Wk, bk, nullptr, p_K);
    sgemm_tn<<<dim3(H_/128, BKV_/128), 256>>>(BKV_, H_, H_, enc, nullptr, Wv, bv, nullptr, p_V);

    // serial LSTM recurrence -> g_H
    rnn_kernel<<<128, 256>>>(W_hh, h0, c0);

    // Q projection
    sgemm_tn<<<dim3(H_/128, BT_/128), 256>>>(BT_, H_, H_, p_H, nullptr, Wq, bq, nullptr, p_Q);

    // attention
    attn_scores_k<<<dim3(SKV_/64, S_/64, B_*NH_), 256>>>(mask);
    softmax_k<<<B_*NH_*S_, 128>>>();
    attn_ctx_k<<<dim3(S_/64, B_*NH_), 256>>>();

    // output projection
    sgemm_tn<<<dim3(H_/128, BT_/128), 256>>>(BT_, H_, H_, p_ctx, nullptr, Wo, bo, nullptr, p_outs);

    // split outs, then tensor-core tied logits: [2048, 32000] = outs @ emb^T
    {
        int n4 = (BT_ * H_) / 4;
        split_bf16_k<<<(n4 + 255) / 256, 256>>>(p_outs, p_ohi, p_olo, n4);
    }
    gemm_logits_bf16<<<dim3(BT_/128, V_/128), 256>>>(p_ohi, p_olo, p_ehi, p_elo, out);
}

// round 8
// speedup vs baseline: 1.3175x; 1.1260x over previous
#include <cuda_runtime.h>
#include <cuda_bf16.h>
#include <math.h>
#include <cstdint>

// ---------------- problem constants ----------------
#define B_    8
#define S_    256
#define SKV_  1024
#define H_    512
#define NH_   8
#define HD_   64
#define G4_   2048            // 4*H
#define V_    32000
#define BT_   (B_*S_)         // 2048
#define BKV_  (B_*SKV_)       // 8192

// ---------------- device scratch (static; allocation is forbidden) --------
__device__ float    g_xg  [BT_  * (size_t)G4_];
__device__ float    g_K   [BKV_ * (size_t)H_];
__device__ float    g_V   [BKV_ * (size_t)H_];
__device__ float    g_H   [BT_  * (size_t)H_];
__device__ float    g_Q   [BT_  * (size_t)H_];
__device__ float    g_ctx [BT_  * (size_t)H_];
__device__ float    g_outs[BT_  * (size_t)H_];
__device__ float    g_hcur[B_ * H_];
__device__ float    g_att [(size_t)B_ * NH_ * S_ * SKV_];
__device__ unsigned g_arrive[4];
// split-bf16 buffers for the tensor-core logits GEMM
__device__ __nv_bfloat16 g_embhi[(size_t)V_ * H_];
__device__ __nv_bfloat16 g_emblo[(size_t)V_ * H_];
__device__ __nv_bfloat16 g_outhi[(size_t)BT_ * H_];
__device__ __nv_bfloat16 g_outlo[(size_t)BT_ * H_];

// ---------------- async-copy helpers ----------------
#define CP_ASYNC16(dst, src) \
    asm volatile("cp.async.cg.shared.global [%0], [%1], 16;" :: "r"(dst), "l"(src))
#define CP_COMMIT() asm volatile("cp.async.commit_group;" ::: "memory")
#define CP_WAIT1()  asm volatile("cp.async.wait_group 1;" ::: "memory")

__device__ __forceinline__ uint32_t smem_u32(const void* p) {
    uint32_t a;
    asm("{ .reg .u64 t; cvta.to.shared.u64 t, %1; cvt.u32.u64 %0, t; }"
        : "=r"(a) : "l"(p));
    return a;
}
#define LDMATRIX_X4(r0, r1, r2, r3, addr) \
    asm volatile("ldmatrix.sync.aligned.m8n8.x4.shared.b16 {%0,%1,%2,%3}, [%4];" \
        : "=r"(r0), "=r"(r1), "=r"(r2), "=r"(r3) : "r"(addr))

// ===========================================================================
// Generic fp32 SGEMM (unchanged, passing)
// ===========================================================================
__global__ void __launch_bounds__(256) sgemm_tn(
    int M, int N, int K,
    const float* __restrict__ A, const int* __restrict__ gidx,
    const float* __restrict__ Bm,
    const float* __restrict__ bias1, const float* __restrict__ bias2,
    float* __restrict__ C)
{
    __shared__ float As[16][132];
    __shared__ float Bs[16][132];
    const int tid = threadIdx.x;
    const int m0 = blockIdx.y * 128, n0 = blockIdx.x * 128;
    const int tm = tid >> 4, tn = tid & 15;

    float acc[8][8];
#pragma unroll
    for (int i = 0; i < 8; i++)
#pragma unroll
        for (int j = 0; j < 8; j++) acc[i][j] = 0.f;

    const int id0 = tid * 2, id1 = tid * 2 + 1;
    const int r0 = id0 >> 2, k0 = (id0 & 3) * 4;
    const int r1 = id1 >> 2, k1 = (id1 & 3) * 4;
    int am0 = m0 + r0; if (gidx) am0 = gidx[am0];
    int am1 = m0 + r1; if (gidx) am1 = gidx[am1];
    const float* Arow0 = A  + (size_t)am0 * K;
    const float* Arow1 = A  + (size_t)am1 * K;
    const float* Brow0 = Bm + (size_t)(n0 + r0) * K;
    const float* Brow1 = Bm + (size_t)(n0 + r1) * K;

    for (int kt = 0; kt < K; kt += 16) {
        float4 a0 = *(const float4*)(Arow0 + kt + k0);
        float4 a1 = *(const float4*)(Arow1 + kt + k1);
        float4 b0 = *(const float4*)(Brow0 + kt + k0);
        float4 b1 = *(const float4*)(Brow1 + kt + k1);
        __syncthreads();
        As[k0+0][r0] = a0.x; As[k0+1][r0] = a0.y; As[k0+2][r0] = a0.z; As[k0+3][r0] = a0.w;
        As[k1+0][r1] = a1.x; As[k1+1][r1] = a1.y; As[k1+2][r1] = a1.z; As[k1+3][r1] = a1.w;
        Bs[k0+0][r0] = b0.x; Bs[k0+1][r0] = b0.y; Bs[k0+2][r0] = b0.z; Bs[k0+3][r0] = b0.w;
        Bs[k1+0][r1] = b1.x; Bs[k1+1][r1] = b1.y; Bs[k1+2][r1] = b1.z; Bs[k1+3][r1] = b1.w;
        __syncthreads();
#pragma unroll
        for (int kk = 0; kk < 16; kk++) {
            const float4* Ap = (const float4*)&As[kk][tm * 8];
            const float4* Bp = (const float4*)&Bs[kk][tn * 8];
            float4 av0 = Ap[0], av1 = Ap[1];
            float4 bv0 = Bp[0], bv1 = Bp[1];
            float a[8] = {av0.x,av0.y,av0.z,av0.w, av1.x,av1.y,av1.z,av1.w};
            float b[8] = {bv0.x,bv0.y,bv0.z,bv0.w, bv1.x,bv1.y,bv1.z,bv1.w};
#pragma unroll
            for (int i = 0; i < 8; i++)
#pragma unroll
                for (int j = 0; j < 8; j++) acc[i][j] += a[i] * b[j];
        }
    }

    float bv[8];
#pragma unroll
    for (int j = 0; j < 8; j++) {
        int n = n0 + tn * 8 + j;
        float t = 0.f;
        if (bias1) t += bias1[n];
        if (bias2) t += bias2[n];
        bv[j] = t;
    }
#pragma unroll
    for (int i = 0; i < 8; i++) {
        int m = m0 + tm * 8 + i;
        float4 o0 = make_float4(acc[i][0]+bv[0], acc[i][1]+bv[1], acc[i][2]+bv[2], acc[i][3]+bv[3]);
        float4 o1 = make_float4(acc[i][4]+bv[4], acc[i][5]+bv[5], acc[i][6]+bv[6], acc[i][7]+bv[7]);
        *(float4*)(C + (size_t)m * N + n0 + tn * 8)     = o0;
        *(float4*)(C + (size_t)m * N + n0 + tn * 8 + 4) = o1;
    }
}

// ===========================================================================
// fp32 -> (bf16 hi, bf16 lo) split
// ===========================================================================
__global__ void __launch_bounds__(256) split_bf16_k(
    const float* __restrict__ x, __nv_bfloat16* __restrict__ hi,
    __nv_bfloat16* __restrict__ lo, int n4)
{
    int i = blockIdx.x * 256 + threadIdx.x;
    if (i >= n4) return;
    float4 v = ((const float4*)x)[i];
    __nv_bfloat16 h0 = __float2bfloat16(v.x), h1 = __float2bfloat16(v.y);
    __nv_bfloat16 h2 = __float2bfloat16(v.z), h3 = __float2bfloat16(v.w);
    __nv_bfloat16 l0 = __float2bfloat16(v.x - __bfloat162float(h0));
    __nv_bfloat16 l1 = __float2bfloat16(v.y - __bfloat162float(h1));
    __nv_bfloat16 l2 = __float2bfloat16(v.z - __bfloat162float(h2));
    __nv_bfloat16 l3 = __float2bfloat16(v.w - __bfloat162float(h3));
    __nv_bfloat162* hp = (__nv_bfloat162*)(hi + (size_t)i * 4);
    __nv_bfloat162* lp = (__nv_bfloat162*)(lo + (size_t)i * 4);
    hp[0] = __nv_bfloat162(h0, h1); hp[1] = __nv_bfloat162(h2, h3);
    lp[0] = __nv_bfloat162(l0, l1); lp[1] = __nv_bfloat162(l2, l3);
}

// ===========================================================================
// Logits GEMM: C[2048][32000] = outs @ emb^T, split-bf16 3-product.
// mma.sync m16n8k16 bf16, cp.async double-buffered, ldmatrix operand loads.
// CTA tile 128x128, BK=32, 48 K-slabs (3 segs x 16). 8 warps (4m x 2n),
// warp tile 32x64. Dynamic smem: 2 stages x (A 10240 + B 10240) = 40960 B.
// grid (16 m fastest, 250 n) for emb-strip L2 reuse.
// ===========================================================================
#define LGS_STAGE 20480      // bytes per stage (A tile + B tile)
#define LGS_BOFF  10240      // B tile offset inside a stage
#define LGS_SMEM  (2 * LGS_STAGE)

__global__ void __launch_bounds__(256, 2) gemm_logits_mma(
    const __nv_bfloat16* __restrict__ Ahi, const __nv_bfloat16* __restrict__ Alo,
    const __nv_bfloat16* __restrict__ Bhi, const __nv_bfloat16* __restrict__ Blo,
    float* __restrict__ C)
{
    extern __shared__ char smem[];
    const uint32_t sbase = smem_u32(smem);
    const int tid  = threadIdx.x;
    const int lane = tid & 31;
    const int warp = tid >> 5;
    const int wm   = warp >> 1, wn = warp & 1;
    const int g    = lane >> 2, t4 = lane & 3;
    const int m0   = blockIdx.x * 128;
    const int n0   = blockIdx.y * 128;

    float acc[2][8][4];
#pragma unroll
    for (int mi = 0; mi < 2; mi++)
#pragma unroll
        for (int ni = 0; ni < 8; ni++)
#pragma unroll
            for (int f = 0; f < 4; f++) acc[mi][ni][f] = 0.f;

    // per-thread cp.async chunk mapping: 2 chunks for A, 2 for B per stage.
    // chunk c (0..511): row = c>>2, k-halfword base = (c&3)*8
    const int c0r = (tid)        >> 2, c0k = ((tid)        & 3) * 8;
    const int c1r = (tid + 256)  >> 2, c1k = ((tid + 256)  & 3) * 8;

    // ldmatrix per-lane base offsets (bytes within a tile)
    const int lm_row = lane & 15;
    const int lm_col = (lane >> 4) * 16;  // byte offset for k-halves 0..7 / 8..15

    auto issue = [&](int t, int buf) {
        const int seg  = t >> 4;
        const int kofs = (t & 15) * 32;
        const __nv_bfloat16* Ap = (seg < 2)  ? Ahi : Alo;
        const __nv_bfloat16* Bp = (seg == 1) ? Blo : Bhi;
        const uint32_t sA = sbase + buf * LGS_STAGE;
        const uint32_t sB = sA + LGS_BOFF;
        CP_ASYNC16(sA + c0r * 80 + c0k * 2, Ap + (size_t)(m0 + c0r) * H_ + kofs + c0k);
        CP_ASYNC16(sA + c1r * 80 + c1k * 2, Ap + (size_t)(m0 + c1r) * H_ + kofs + c1k);
        CP_ASYNC16(sB + c0r * 80 + c0k * 2, Bp + (size_t)(n0 + c0r) * H_ + kofs + c0k);
        CP_ASYNC16(sB + c1r * 80 + c1k * 2, Bp + (size_t)(n0 + c1r) * H_ + kofs + c1k);
    };

    issue(0, 0);
    CP_COMMIT();

    for (int t = 0; t < 48; t++) {
        if (t + 1 < 48) issue(t + 1, (t + 1) & 1);
        CP_COMMIT();
        CP_WAIT1();
        __syncthreads();

        const uint32_t sA = sbase + (t & 1) * LGS_STAGE;
        const uint32_t sB = sA + LGS_BOFF;

#pragma unroll
        for (int k0 = 0; k0 < 2; k0++) {           // k halves of BK=32
            const uint32_t kb = k0 * 32 + lm_col;  // byte offset in row
            uint32_t a[2][4];
#pragma unroll
            for (int mi = 0; mi < 2; mi++) {
                uint32_t addr = sA + (uint32_t)(wm * 32 + mi * 16 + lm_row) * 80 + kb;
                LDMATRIX_X4(a[mi][0], a[mi][1], a[mi][2], a[mi][3], addr);
            }
            uint32_t bf[4][4];
#pragma unroll
            for (int nj = 0; nj < 4; nj++) {
                uint32_t addr = sB + (uint32_t)(wn * 64 + nj * 16 + lm_row) * 80 + kb;
                LDMATRIX_X4(bf[nj][0], bf[nj][1], bf[nj][2], bf[nj][3], addr);
            }
#pragma unroll
            for (int nj = 0; nj < 4; nj++) {
#pragma unroll
                for (int hh = 0; hh < 2; hh++) {
                    const int ni = nj * 2 + hh;
                    uint32_t b0 = bf[nj][hh], b1 = bf[nj][hh + 2];
#pragma unroll
                    for (int mi = 0; mi < 2; mi++) {
                        asm volatile(
                            "mma.sync.aligned.m16n8k16.row.col.f32.bf16.bf16.f32 "
                            "{%0,%1,%2,%3}, {%4,%5,%6,%7}, {%8,%9}, {%0,%1,%2,%3};\n"
                            : "+f"(acc[mi][ni][0]), "+f"(acc[mi][ni][1]),
                              "+f"(acc[mi][ni][2]), "+f"(acc[mi][ni][3])
                            : "r"(a[mi][0]), "r"(a[mi][1]), "r"(a[mi][2]), "r"(a[mi][3]),
                              "r"(b0), "r"(b1));
                    }
                }
            }
        }
        __syncthreads();
    }

#pragma unroll
    for (int mi = 0; mi < 2; mi++) {
#pragma unroll
        for (int ni = 0; ni < 8; ni++) {
            int row = m0 + wm * 32 + mi * 16 + g;
            int col = n0 + wn * 64 + ni * 8 + 2 * t4;
            float2 v0 = make_float2(acc[mi][ni][0], acc[mi][ni][1]);
            float2 v1 = make_float2(acc[mi][ni][2], acc[mi][ni][3]);
            *(float2*)&C[(size_t)row * V_ + col]       = v0;
            *(float2*)&C[(size_t)(row + 8) * V_ + col] = v1;
        }
    }
}

// ===========================================================================
// Reset kernel
// ===========================================================================
__global__ void reset_k()
{
    if (threadIdx.x < 4) g_arrive[threadIdx.x] = 0u;
}

// ===========================================================================
// Persistent LSTM recurrence (unchanged, passing)
// ===========================================================================
__device__ __forceinline__ float sigm(float x) { return 1.f / (1.f + expf(-x)); }

__global__ void __launch_bounds__(256, 1) rnn_kernel(
    const float* __restrict__ W_hh, const float* __restrict__ h0,
    const float* __restrict__ c0)
{
    const int cta  = blockIdx.x;
    const int pair = cta >> 5;
    const int grp  = cta & 31;
    const int tid  = threadIdx.x;
    const int q    = tid >> 6;
    const int r    = tid & 63;
    const int gate = r >> 4, uu = r & 15;
    const int unit = grp * 16 + uu;

    __shared__ float h_sm[2][H_];
    __shared__ float red[4][64][2];
    __shared__ float gsm[64][2];
    __shared__ float c_sm[2][16];

    float w[128];
    {
        const float4* wp = (const float4*)(W_hh + (size_t)(gate * H_ + unit) * H_ + q * 128);
#pragma unroll
        for (int j = 0; j < 32; j++) {
            float4 v = wp[j];
            w[4*j+0] = v.x; w[4*j+1] = v.y; w[4*j+2] = v.z; w[4*j+3] = v.w;
        }
    }

    for (int s = 0; s < S_; s++) {
        {
            const int bb = tid >> 7, off = (tid & 127) * 4;
            float4 v;
            if (s == 0) v = *(const float4*)(h0 + (size_t)(pair*2 + bb) * H_ + off);
            else        v = __ldcg((const float4*)(g_hcur + (size_t)(pair*2 + bb) * H_ + off));
            *(float4*)&h_sm[bb][off] = v;
        }
        if (s == 0 && tid < 32) {
            int b2 = tid >> 4, u2 = tid & 15;
            c_sm[b2][u2] = c0[(size_t)(pair*2 + b2) * H_ + grp*16 + u2];
        }
        __syncthreads();

        float a0 = 0.f, a1 = 0.f;
        {
            const float* hp0 = &h_sm[0][q * 128];
            const float* hp1 = &h_sm[1][q * 128];
#pragma unroll
            for (int j = 0; j < 128; j++) {
                a0 += w[j] * hp0[j];
                a1 += w[j] * hp1[j];
            }
        }
        red[q][r][0] = a0;
        red[q][r][1] = a1;
        __syncthreads();

        if (tid < 128) {
            const int rr = tid >> 1, bb = tid & 1;
            const int gg = rr >> 4, u2 = rr & 15;
            float g = red[0][rr][bb] + red[1][rr][bb] + red[2][rr][bb] + red[3][rr][bb]
                    + g_xg[((size_t)(pair*2 + bb) * S_ + s) * G4_ + gg * H_ + grp*16 + u2];
            gsm[rr][bb] = g;
        }
        __syncthreads();

        if (tid < 32) {
            const int bb = tid >> 4, u2 = tid & 15;
            float iv = gsm[ 0 + u2][bb];
            float fv = gsm[16 + u2][bb];
            float gv = gsm[32 + u2][bb];
            float ov = gsm[48 + u2][bb];
            float cn = sigm(fv) * c_sm[bb][u2] + sigm(iv) * tanhf(gv);
            float hn = sigm(ov) * tanhf(cn);
            c_sm[bb][u2] = cn;
            const int bg = pair*2 + bb, un = grp*16 + u2;
            g_hcur[(size_t)bg * H_ + un] = hn;
            g_H[((size_t)bg * S_ + s) * H_ + un] = hn;
            __threadfence();
        }
        __syncthreads();

        if (tid == 0) {
            atomicAdd(&g_arrive[pair], 1u);
            const unsigned target = 32u * (unsigned)(s + 1);
            while (*((volatile unsigned*)&g_arrive[pair]) < target) { }
        }
        __syncthreads();
        __threadfence();
    }
}

// ===========================================================================
// Attention scores (unchanged)
// ===========================================================================
__global__ void __launch_bounds__(256) attn_scores_k(const int* __restrict__ mask)
{
    __shared__ float Qs[64][65];
    __shared__ float Ks[64][65];
    const int bh = blockIdx.z, b = bh >> 3, h = bh & 7;
    const int s0 = blockIdx.y * 64, k0 = blockIdx.x * 64;
    const int tid = threadIdx.x;

    for (int e = tid; e < 64 * 64; e += 256) {
        int row = e >> 6, col = e & 63;
        Qs[row][col] = g_Q[((size_t)b * S_ + s0 + row) * H_ + h * HD_ + col];
        Ks[row][col] = g_K[((size_t)b * SKV_ + k0 + row) * H_ + h * HD_ + col];
    }
    __syncthreads();

    const int tm = tid >> 4, tn = tid & 15;
    float acc[4][4];
#pragma unroll
    for (int i = 0; i < 4; i++)
#pragma unroll
        for (int j = 0; j < 4; j++) acc[i][j] = 0.f;

#pragma unroll 8
    for (int d = 0; d < 64; d++) {
        float a[4], bb[4];
#pragma unroll
        for (int i = 0; i < 4; i++) a[i]  = Qs[tm*4 + i][d];
#pragma unroll
        for (int j = 0; j < 4; j++) bb[j] = Ks[tn*4 + j][d];
#pragma unroll
        for (int i = 0; i < 4; i++)
#pragma unroll
            for (int j = 0; j < 4; j++) acc[i][j] += a[i] * bb[j];
    }

    const float scale = 0.125f;
#pragma unroll
    for (int i = 0; i < 4; i++) {
        int s = s0 + tm*4 + i;
#pragma unroll
        for (int j = 0; j < 4; j++) {
            int k = k0 + tn*4 + j;
            float v = acc[i][j] * scale;
            if (mask[b * SKV_ + k] != 1) v = -1e9f;
            g_att[((size_t)bh * S_ + s) * SKV_ + k] = v;
        }
    }
}

// ===========================================================================
// Softmax (unchanged)
// ===========================================================================
__global__ void __launch_bounds__(128) softmax_k()
{
    const size_t base = (size_t)blockIdx.x * SKV_;
    const int tid = threadIdx.x;
    float v[8];
    float mx = -1e30f;
#pragma unroll
    for (int i = 0; i < 8; i++) {
        v[i] = g_att[base + tid + i * 128];
        mx = fmaxf(mx, v[i]);
    }
    __shared__ float sm[4];
#pragma unroll
    for (int off = 16; off > 0; off >>= 1)
        mx = fmaxf(mx, __shfl_xor_sync(0xffffffffu, mx, off));
    if ((tid & 31) == 0) sm[tid >> 5] = mx;
    __syncthreads();
    mx = fmaxf(fmaxf(sm[0], sm[1]), fmaxf(sm[2], sm[3]));

    float sum = 0.f;
#pragma unroll
    for (int i = 0; i < 8; i++) { v[i] = expf(v[i] - mx); sum += v[i]; }
#pragma unroll
    for (int off = 16; off > 0; off >>= 1)
        sum += __shfl_xor_sync(0xffffffffu, sum, off);
    __syncthreads();
    if ((tid & 31) == 0) sm[tid >> 5] = sum;
    __syncthreads();
    sum = sm[0] + sm[1] + sm[2] + sm[3];
    const float inv = 1.f / sum;
#pragma unroll
    for (int i = 0; i < 8; i++) g_att[base + tid + i * 128] = v[i] * inv;
}

// ===========================================================================
// attn @ V (unchanged)
// ===========================================================================
__global__ void __launch_bounds__(256) attn_ctx_k()
{
    __shared__ float As[64][65];
    __shared__ float Vs[64][65];
    const int bh = blockIdx.y, b = bh >> 3, h = bh & 7;
    const int s0 = blockIdx.x * 64;
    const int tid = threadIdx.x;
    const int tm = tid >> 4, tn = tid & 15;

    float acc[4][4];
#pragma unroll
    for (int i = 0; i < 4; i++)
#pragma unroll
        for (int j = 0; j < 4; j++) acc[i][j] = 0.f;

    for (int kt = 0; kt < SKV_; kt += 64) {
        for (int e = tid; e < 64 * 64; e += 256) {
            int row = e >> 6, col = e & 63;
            As[row][col] = g_att[((size_t)bh * S_ + s0 + row) * SKV_ + kt + col];
            Vs[row][col] = g_V[((size_t)b * SKV_ + kt + row) * H_ + h * HD_ + col];
        }
        __syncthreads();
#pragma unroll 8
        for (int kk = 0; kk < 64; kk++) {
            float a[4], vv[4];
#pragma unroll
            for (int i = 0; i < 4; i++) a[i]  = As[tm*4 + i][kk];
#pragma unroll
            for (int j = 0; j < 4; j++) vv[j] = Vs[kk][tn*4 + j];
#pragma unroll
            for (int i = 0; i < 4; i++)
#pragma unroll
                for (int j = 0; j < 4; j++) acc[i][j] += a[i] * vv[j];
        }
        __syncthreads();
    }

#pragma unroll
    for (int i = 0; i < 4; i++) {
        int s = s0 + tm*4 + i;
#pragma unroll
        for (int j = 0; j < 4; j++)
            g_ctx[((size_t)b * S_ + s) * H_ + h * HD_ + tn*4 + j] = acc[i][j];
    }
}

// ===========================================================================
// Host orchestration
// ===========================================================================
extern "C" void kernel_launch(void* const* d_in, const int* in_sizes, int n_in,
                              void* d_out, int out_size)
{
    const int*   tok   = (const int*)  d_in[0];
    const float* enc   = (const float*)d_in[1];
    const int*   mask  = (const int*)  d_in[2];
    const float* emb   = (const float*)d_in[3];
    const float* W_ih  = (const float*)d_in[4];
    const float* W_hh  = (const float*)d_in[5];
    const float* b_ih  = (const float*)d_in[6];
    const float* b_hh  = (const float*)d_in[7];
    const float* Wq    = (const float*)d_in[8];
    const float* bq    = (const float*)d_in[9];
    const float* Wk    = (const float*)d_in[10];
    const float* bk    = (const float*)d_in[11];
    const float* Wv    = (const float*)d_in[12];
    const float* bv    = (const float*)d_in[13];
    const float* Wo    = (const float*)d_in[14];
    const float* bo    = (const float*)d_in[15];
    const float* h0    = (const float*)d_in[16];
    const float* c0    = (const float*)d_in[17];
    float* out = (float*)d_out;

    float *p_xg, *p_K, *p_V, *p_H, *p_Q, *p_ctx, *p_outs;
    __nv_bfloat16 *p_ehi, *p_elo, *p_ohi, *p_olo;
    cudaGetSymbolAddress((void**)&p_xg,   g_xg);
    cudaGetSymbolAddress((void**)&p_K,    g_K);
    cudaGetSymbolAddress((void**)&p_V,    g_V);
    cudaGetSymbolAddress((void**)&p_H,    g_H);
    cudaGetSymbolAddress((void**)&p_Q,    g_Q);
    cudaGetSymbolAddress((void**)&p_ctx,  g_ctx);
    cudaGetSymbolAddress((void**)&p_outs, g_outs);
    cudaGetSymbolAddress((void**)&p_ehi,  g_embhi);
    cudaGetSymbolAddress((void**)&p_elo,  g_emblo);
    cudaGetSymbolAddress((void**)&p_ohi,  g_outhi);
    cudaGetSymbolAddress((void**)&p_olo,  g_outlo);

    cudaFuncSetAttribute(gemm_logits_mma,
                         cudaFuncAttributeMaxDynamicSharedMemorySize, LGS_SMEM);

    reset_k<<<1, 32>>>();

    // split emb into bf16 hi/lo (independent of everything else)
    {
        int n4 = (V_ * H_) / 4;
        split_bf16_k<<<(n4 + 255) / 256, 256>>>(emb, p_ehi, p_elo, n4);
    }

    // x-gates with fused embedding gather
    sgemm_tn<<<dim3(G4_/128, BT_/128), 256>>>(BT_, G4_, H_, emb, tok, W_ih, b_ih, b_hh, p_xg);
    // encoder K/V projections
    sgemm_tn<<<dim3(H_/128, BKV_/128), 256>>>(BKV_, H_, H_, enc, nullptr, Wk, bk, nullptr, p_K);
    sgemm_tn<<<dim3(H_/128, BKV_/128), 256>>>(BKV_, H_, H_, enc, nullptr, Wv, bv, nullptr, p_V);

    // serial LSTM recurrence -> g_H
    rnn_kernel<<<128, 256>>>(W_hh, h0, c0);

    // Q projection
    sgemm_tn<<<dim3(H_/128, BT_/128), 256>>>(BT_, H_, H_, p_H, nullptr, Wq, bq, nullptr, p_Q);

    // attention
    attn_scores_k<<<dim3(SKV_/64, S_/64, B_*NH_), 256>>>(mask);
    softmax_k<<<B_*NH_*S_, 128>>>();
    attn_ctx_k<<<dim3(S_/64, B_*NH_), 256>>>();

    // output projection
    sgemm_tn<<<dim3(H_/128, BT_/128), 256>>>(BT_, H_, H_, p_ctx, nullptr, Wo, bo, nullptr, p_outs);

    // split outs, then bf16 mma tied logits
    {
        int n4 = (BT_ * H_) / 4;
        split_bf16_k<<<(n4 + 255) / 256, 256>>>(p_outs, p_ohi, p_olo, n4);
    }
    gemm_logits_mma<<<dim3(BT_/128, V_/128), 256, LGS_SMEM>>>(
        p_ohi, p_olo, p_ehi, p_elo, out);
}

// round 10
// speedup vs baseline: 1.4055x; 1.0668x over previous
#include <cuda_runtime.h>
#include <cuda_bf16.h>
#include <math.h>
#include <cstdint>

// ---------------- problem constants ----------------
#define B_    8
#define S_    256
#define SKV_  1024
#define H_    512
#define NH_   8
#define HD_   64
#define G4_   2048            // 4*H
#define V_    32000
#define BT_   (B_*S_)         // 2048
#define BKV_  (B_*SKV_)       // 8192
#define K_GEMM 512            // shared K dim of every dense GEMM here

// ---------------- device scratch (static; allocation is forbidden) --------
__device__ float    g_xg  [BT_  * (size_t)G4_];
__device__ float    g_K   [BKV_ * (size_t)H_];
__device__ float    g_V   [BKV_ * (size_t)H_];
__device__ float    g_H   [BT_  * (size_t)H_];
__device__ float    g_Q   [BT_  * (size_t)H_];
__device__ float    g_ctx [BT_  * (size_t)H_];
__device__ float    g_outs[BT_  * (size_t)H_];
__device__ float    g_hcur[B_ * H_];
__device__ float    g_att [(size_t)B_ * NH_ * S_ * SKV_];
__device__ unsigned g_arrive[4];
// split-bf16 operand buffers
__device__ __nv_bfloat16 g_embhi[(size_t)V_ * H_];
__device__ __nv_bfloat16 g_emblo[(size_t)V_ * H_];
__device__ __nv_bfloat16 g_outhi[(size_t)BT_ * H_];
__device__ __nv_bfloat16 g_outlo[(size_t)BT_ * H_];
__device__ __nv_bfloat16 g_enchi[(size_t)BKV_ * H_];
__device__ __nv_bfloat16 g_enclo[(size_t)BKV_ * H_];
__device__ __nv_bfloat16 g_wihhi[(size_t)G4_ * H_];
__device__ __nv_bfloat16 g_wihlo[(size_t)G4_ * H_];
__device__ __nv_bfloat16 g_wqhi[(size_t)H_ * H_];
__device__ __nv_bfloat16 g_wqlo[(size_t)H_ * H_];
__device__ __nv_bfloat16 g_wkhi[(size_t)H_ * H_];
__device__ __nv_bfloat16 g_wklo[(size_t)H_ * H_];
__device__ __nv_bfloat16 g_wvhi[(size_t)H_ * H_];
__device__ __nv_bfloat16 g_wvlo[(size_t)H_ * H_];
__device__ __nv_bfloat16 g_wohi[(size_t)H_ * H_];
__device__ __nv_bfloat16 g_wolo[(size_t)H_ * H_];
__device__ __nv_bfloat16 g_Hhi [(size_t)BT_ * H_];
__device__ __nv_bfloat16 g_Hlo [(size_t)BT_ * H_];
__device__ __nv_bfloat16 g_ctxhi[(size_t)BT_ * H_];
__device__ __nv_bfloat16 g_ctxlo[(size_t)BT_ * H_];

// ---------------- async-copy / ldmatrix helpers ----------------
#define CP_ASYNC16(dst, src) \
    asm volatile("cp.async.cg.shared.global [%0], [%1], 16;" :: "r"(dst), "l"(src))
#define CP_COMMIT() asm volatile("cp.async.commit_group;" ::: "memory")
#define CP_WAIT1()  asm volatile("cp.async.wait_group 1;" ::: "memory")

__device__ __forceinline__ uint32_t smem_u32(const void* p) {
    uint32_t a;
    asm("{ .reg .u64 t; cvta.to.shared.u64 t, %1; cvt.u32.u64 %0, t; }"
        : "=r"(a) : "l"(p));
    return a;
}
#define LDMATRIX_X4(r0, r1, r2, r3, addr) \
    asm volatile("ldmatrix.sync.aligned.m8n8.x4.shared.b16 {%0,%1,%2,%3}, [%4];" \
        : "=r"(r0), "=r"(r1), "=r"(r2), "=r"(r3) : "r"(addr))

// ===========================================================================
// fp32 -> (bf16 hi, bf16 lo) split
// ===========================================================================
__global__ void __launch_bounds__(256) split_bf16_k(
    const float* __restrict__ x, __nv_bfloat16* __restrict__ hi,
    __nv_bfloat16* __restrict__ lo, int n4)
{
    int i = blockIdx.x * 256 + threadIdx.x;
    if (i >= n4) return;
    float4 v = ((const float4*)x)[i];
    __nv_bfloat16 h0 = __float2bfloat16(v.x), h1 = __float2bfloat16(v.y);
    __nv_bfloat16 h2 = __float2bfloat16(v.z), h3 = __float2bfloat16(v.w);
    __nv_bfloat16 l0 = __float2bfloat16(v.x - __bfloat162float(h0));
    __nv_bfloat16 l1 = __float2bfloat16(v.y - __bfloat162float(h1));
    __nv_bfloat16 l2 = __float2bfloat16(v.z - __bfloat162float(h2));
    __nv_bfloat16 l3 = __float2bfloat16(v.w - __bfloat162float(h3));
    __nv_bfloat162* hp = (__nv_bfloat162*)(hi + (size_t)i * 4);
    __nv_bfloat162* lp = (__nv_bfloat162*)(lo + (size_t)i * 4);
    hp[0] = __nv_bfloat162(h0, h1); hp[1] = __nv_bfloat162(h2, h3);
    lp[0] = __nv_bfloat162(l0, l1); lp[1] = __nv_bfloat162(l2, l3);
}

// ===========================================================================
// Split-bf16 TN GEMM (3-product): C[m][n] = sum_k A'[m][k]*B[n][k] (+bias)
//   A' rows optionally gathered via gidx. K fixed = 512 (3 segs x 16 slabs).
//   mma.sync m16n8k16 bf16 + cp.async double buffer + ldmatrix.
//   CTA tile 128x128, 8 warps (4m x 2n), warp tile 32x64.
//   grid = (M/128, N/128); dynamic smem 40960 B.
// ===========================================================================
#define LGS_STAGE 20480
#define LGS_BOFF  10240
#define LGS_SMEM  (2 * LGS_STAGE)

__global__ void __launch_bounds__(256, 2) hgemm_tn_mma(
    int ldc,
    const __nv_bfloat16* __restrict__ Ahi, const __nv_bfloat16* __restrict__ Alo,
    const int* __restrict__ gidx,
    const __nv_bfloat16* __restrict__ Bhi, const __nv_bfloat16* __restrict__ Blo,
    const float* __restrict__ bias1, const float* __restrict__ bias2,
    float* __restrict__ C)
{
    extern __shared__ char smem[];
    const uint32_t sbase = smem_u32(smem);
    const int tid  = threadIdx.x;
    const int lane = tid & 31;
    const int warp = tid >> 5;
    const int wm   = warp >> 1, wn = warp & 1;
    const int g    = lane >> 2, t4 = lane & 3;
    const int m0   = blockIdx.x * 128;
    const int n0   = blockIdx.y * 128;

    float acc[2][8][4];
#pragma unroll
    for (int mi = 0; mi < 2; mi++)
#pragma unroll
        for (int ni = 0; ni < 8; ni++)
#pragma unroll
            for (int f = 0; f < 4; f++) acc[mi][ni][f] = 0.f;

    // per-thread cp.async chunk mapping (row indices are loop-invariant)
    const int c0r = (tid)       >> 2, c0k = ((tid)       & 3) * 8;
    const int c1r = (tid + 256) >> 2, c1k = ((tid + 256) & 3) * 8;
    int ar0 = m0 + c0r, ar1 = m0 + c1r;
    if (gidx) { ar0 = gidx[ar0]; ar1 = gidx[ar1]; }
    const int br0 = n0 + c0r, br1 = n0 + c1r;

    const int lm_row = lane & 15;
    const int lm_col = (lane >> 4) * 16;

    auto issue = [&](int t, int buf) {
        const int seg  = t >> 4;
        const int kofs = (t & 15) * 32;
        const __nv_bfloat16* Ap = (seg < 2)  ? Ahi : Alo;
        const __nv_bfloat16* Bp = (seg == 1) ? Blo : Bhi;
        const uint32_t sA = sbase + buf * LGS_STAGE;
        const uint32_t sB = sA + LGS_BOFF;
        CP_ASYNC16(sA + c0r * 80 + c0k * 2, Ap + (size_t)ar0 * K_GEMM + kofs + c0k);
        CP_ASYNC16(sA + c1r * 80 + c1k * 2, Ap + (size_t)ar1 * K_GEMM + kofs + c1k);
        CP_ASYNC16(sB + c0r * 80 + c0k * 2, Bp + (size_t)br0 * K_GEMM + kofs + c0k);
        CP_ASYNC16(sB + c1r * 80 + c1k * 2, Bp + (size_t)br1 * K_GEMM + kofs + c1k);
    };

    issue(0, 0);
    CP_COMMIT();

    for (int t = 0; t < 48; t++) {
        if (t + 1 < 48) issue(t + 1, (t + 1) & 1);
        CP_COMMIT();
        CP_WAIT1();
        __syncthreads();

        const uint32_t sA = sbase + (t & 1) * LGS_STAGE;
        const uint32_t sB = sA + LGS_BOFF;

#pragma unroll
        for (int k0 = 0; k0 < 2; k0++) {
            const uint32_t kb = k0 * 32 + lm_col;
            uint32_t a[2][4];
#pragma unroll
            for (int mi = 0; mi < 2; mi++) {
                uint32_t addr = sA + (uint32_t)(wm * 32 + mi * 16 + lm_row) * 80 + kb;
                LDMATRIX_X4(a[mi][0], a[mi][1], a[mi][2], a[mi][3], addr);
            }
            uint32_t bf[4][4];
#pragma unroll
            for (int nj = 0; nj < 4; nj++) {
                uint32_t addr = sB + (uint32_t)(wn * 64 + nj * 16 + lm_row) * 80 + kb;
                LDMATRIX_X4(bf[nj][0], bf[nj][1], bf[nj][2], bf[nj][3], addr);
            }
#pragma unroll
            for (int nj = 0; nj < 4; nj++) {
#pragma unroll
                for (int hh = 0; hh < 2; hh++) {
                    const int ni = nj * 2 + hh;
                    uint32_t b0 = bf[nj][hh], b1 = bf[nj][hh + 2];
#pragma unroll
                    for (int mi = 0; mi < 2; mi++) {
                        asm volatile(
                            "mma.sync.aligned.m16n8k16.row.col.f32.bf16.bf16.f32 "
                            "{%0,%1,%2,%3}, {%4,%5,%6,%7}, {%8,%9}, {%0,%1,%2,%3};\n"
                            : "+f"(acc[mi][ni][0]), "+f"(acc[mi][ni][1]),
                              "+f"(acc[mi][ni][2]), "+f"(acc[mi][ni][3])
                            : "r"(a[mi][0]), "r"(a[mi][1]), "r"(a[mi][2]), "r"(a[mi][3]),
                              "r"(b0), "r"(b1));
                    }
                }
            }
        }
        __syncthreads();
    }

#pragma unroll
    for (int mi = 0; mi < 2; mi++) {
#pragma unroll
        for (int ni = 0; ni < 8; ni++) {
            int row = m0 + wm * 32 + mi * 16 + g;
            int col = n0 + wn * 64 + ni * 8 + 2 * t4;
            float b0 = 0.f, b1 = 0.f;
            if (bias1) { b0 = bias1[col]; b1 = bias1[col + 1]; }
            if (bias2) { b0 += bias2[col]; b1 += bias2[col + 1]; }
            float2 v0 = make_float2(acc[mi][ni][0] + b0, acc[mi][ni][1] + b1);
            float2 v1 = make_float2(acc[mi][ni][2] + b0, acc[mi][ni][3] + b1);
            *(float2*)&C[(size_t)row * ldc + col]       = v0;
            *(float2*)&C[(size_t)(row + 8) * ldc + col] = v1;
        }
    }
}

// ===========================================================================
// Reset kernel
// ===========================================================================
__global__ void reset_k()
{
    if (threadIdx.x < 4) g_arrive[threadIdx.x] = 0u;
}

// ===========================================================================
// Persistent LSTM recurrence (unchanged, passing)
// ===========================================================================
__device__ __forceinline__ float sigm(float x) { return 1.f / (1.f + expf(-x)); }

__global__ void __launch_bounds__(256, 1) rnn_kernel(
    const float* __restrict__ W_hh, const float* __restrict__ h0,
    const float* __restrict__ c0)
{
    const int cta  = blockIdx.x;
    const int pair = cta >> 5;
    const int grp  = cta & 31;
    const int tid  = threadIdx.x;
    const int q    = tid >> 6;
    const int r    = tid & 63;
    const int gate = r >> 4, uu = r & 15;
    const int unit = grp * 16 + uu;

    __shared__ float h_sm[2][H_];
    __shared__ float red[4][64][2];
    __shared__ float gsm[64][2];
    __shared__ float c_sm[2][16];

    float w[128];
    {
        const float4* wp = (const float4*)(W_hh + (size_t)(gate * H_ + unit) * H_ + q * 128);
#pragma unroll
        for (int j = 0; j < 32; j++) {
            float4 v = wp[j];
            w[4*j+0] = v.x; w[4*j+1] = v.y; w[4*j+2] = v.z; w[4*j+3] = v.w;
        }
    }

    for (int s = 0; s < S_; s++) {
        {
            const int bb = tid >> 7, off = (tid & 127) * 4;
            float4 v;
            if (s == 0) v = *(const float4*)(h0 + (size_t)(pair*2 + bb) * H_ + off);
            else        v = __ldcg((const float4*)(g_hcur + (size_t)(pair*2 + bb) * H_ + off));
            *(float4*)&h_sm[bb][off] = v;
        }
        if (s == 0 && tid < 32) {
            int b2 = tid >> 4, u2 = tid & 15;
            c_sm[b2][u2] = c0[(size_t)(pair*2 + b2) * H_ + grp*16 + u2];
        }
        __syncthreads();

        float a0 = 0.f, a1 = 0.f;
        {
            const float* hp0 = &h_sm[0][q * 128];
            const float* hp1 = &h_sm[1][q * 128];
#pragma unroll
            for (int j = 0; j < 128; j++) {
                a0 += w[j] * hp0[j];
                a1 += w[j] * hp1[j];
            }
        }
        red[q][r][0] = a0;
        red[q][r][1] = a1;
        __syncthreads();

        if (tid < 128) {
            const int rr = tid >> 1, bb = tid & 1;
            const int gg = rr >> 4, u2 = rr & 15;
            float g = red[0][rr][bb] + red[1][rr][bb] + red[2][rr][bb] + red[3][rr][bb]
                    + g_xg[((size_t)(pair*2 + bb) * S_ + s) * G4_ + gg * H_ + grp*16 + u2];
            gsm[rr][bb] = g;
        }
        __syncthreads();

        if (tid < 32) {
            const int bb = tid >> 4, u2 = tid & 15;
            float iv = gsm[ 0 + u2][bb];
            float fv = gsm[16 + u2][bb];
            float gv = gsm[32 + u2][bb];
            float ov = gsm[48 + u2][bb];
            float cn = sigm(fv) * c_sm[bb][u2] + sigm(iv) * tanhf(gv);
            float hn = sigm(ov) * tanhf(cn);
            c_sm[bb][u2] = cn;
            const int bg = pair*2 + bb, un = grp*16 + u2;
            g_hcur[(size_t)bg * H_ + un] = hn;
            g_H[((size_t)bg * S_ + s) * H_ + un] = hn;
            __threadfence();
        }
        __syncthreads();

        if (tid == 0) {
            atomicAdd(&g_arrive[pair], 1u);
            const unsigned target = 32u * (unsigned)(s + 1);
            while (*((volatile unsigned*)&g_arrive[pair]) < target) { }
        }
        __syncthreads();
        __threadfence();
    }
}

// ===========================================================================
// Attention scores (unchanged)
// ===========================================================================
__global__ void __launch_bounds__(256) attn_scores_k(const int* __restrict__ mask)
{
    __shared__ float Qs[64][65];
    __shared__ float Ks[64][65];
    const int bh = blockIdx.z, b = bh >> 3, h = bh & 7;
    const int s0 = blockIdx.y * 64, k0 = blockIdx.x * 64;
    const int tid = threadIdx.x;

    for (int e = tid; e < 64 * 64; e += 256) {
        int row = e >> 6, col = e & 63;
        Qs[row][col] = g_Q[((size_t)b * S_ + s0 + row) * H_ + h * HD_ + col];
        Ks[row][col] = g_K[((size_t)b * SKV_ + k0 + row) * H_ + h * HD_ + col];
    }
    __syncthreads();

    const int tm = tid >> 4, tn = tid & 15;
    float acc[4][4];
#pragma unroll
    for (int i = 0; i < 4; i++)
#pragma unroll
        for (int j = 0; j < 4; j++) acc[i][j] = 0.f;

#pragma unroll 8
    for (int d = 0; d < 64; d++) {
        float a[4], bb[4];
#pragma unroll
        for (int i = 0; i < 4; i++) a[i]  = Qs[tm*4 + i][d];
#pragma unroll
        for (int j = 0; j < 4; j++) bb[j] = Ks[tn*4 + j][d];
#pragma unroll
        for (int i = 0; i < 4; i++)
#pragma unroll
            for (int j = 0; j < 4; j++) acc[i][j] += a[i] * bb[j];
    }

    const float scale = 0.125f;
#pragma unroll
    for (int i = 0; i < 4; i++) {
        int s = s0 + tm*4 + i;
#pragma unroll
        for (int j = 0; j < 4; j++) {
            int k = k0 + tn*4 + j;
            float v = acc[i][j] * scale;
            if (mask[b * SKV_ + k] != 1) v = -1e9f;
            g_att[((size_t)bh * S_ + s) * SKV_ + k] = v;
        }
    }
}

// ===========================================================================
// Softmax (unchanged)
// ===========================================================================
__global__ void __launch_bounds__(128) softmax_k()
{
    const size_t base = (size_t)blockIdx.x * SKV_;
    const int tid = threadIdx.x;
    float v[8];
    float mx = -1e30f;
#pragma unroll
    for (int i = 0; i < 8; i++) {
        v[i] = g_att[base + tid + i * 128];
        mx = fmaxf(mx, v[i]);
    }
    __shared__ float sm[4];
#pragma unroll
    for (int off = 16; off > 0; off >>= 1)
        mx = fmaxf(mx, __shfl_xor_sync(0xffffffffu, mx, off));
    if ((tid & 31) == 0) sm[tid >> 5] = mx;
    __syncthreads();
    mx = fmaxf(fmaxf(sm[0], sm[1]), fmaxf(sm[2], sm[3]));

    float sum = 0.f;
#pragma unroll
    for (int i = 0; i < 8; i++) { v[i] = expf(v[i] - mx); sum += v[i]; }
#pragma unroll
    for (int off = 16; off > 0; off >>= 1)
        sum += __shfl_xor_sync(0xffffffffu, sum, off);
    __syncthreads();
    if ((tid & 31) == 0) sm[tid >> 5] = sum;
    __syncthreads();
    sum = sm[0] + sm[1] + sm[2] + sm[3];
    const float inv = 1.f / sum;
#pragma unroll
    for (int i = 0; i < 8; i++) g_att[base + tid + i * 128] = v[i] * inv;
}

// ===========================================================================
// attn @ V (unchanged)
// ===========================================================================
__global__ void __launch_bounds__(256) attn_ctx_k()
{
    __shared__ float As[64][65];
    __shared__ float Vs[64][65];
    const int bh = blockIdx.y, b = bh >> 3, h = bh & 7;
    const int s0 = blockIdx.x * 64;
    const int tid = threadIdx.x;
    const int tm = tid >> 4, tn = tid & 15;

    float acc[4][4];
#pragma unroll
    for (int i = 0; i < 4; i++)
#pragma unroll
        for (int j = 0; j < 4; j++) acc[i][j] = 0.f;

    for (int kt = 0; kt < SKV_; kt += 64) {
        for (int e = tid; e < 64 * 64; e += 256) {
            int row = e >> 6, col = e & 63;
            As[row][col] = g_att[((size_t)bh * S_ + s0 + row) * SKV_ + kt + col];
            Vs[row][col] = g_V[((size_t)b * SKV_ + kt + row) * H_ + h * HD_ + col];
        }
        __syncthreads();
#pragma unroll 8
        for (int kk = 0; kk < 64; kk++) {
            float a[4], vv[4];
#pragma unroll
            for (int i = 0; i < 4; i++) a[i]  = As[tm*4 + i][kk];
#pragma unroll
            for (int j = 0; j < 4; j++) vv[j] = Vs[kk][tn*4 + j];
#pragma unroll
            for (int i = 0; i < 4; i++)
#pragma unroll
                for (int j = 0; j < 4; j++) acc[i][j] += a[i] * vv[j];
        }
        __syncthreads();
    }

#pragma unroll
    for (int i = 0; i < 4; i++) {
        int s = s0 + tm*4 + i;
#pragma unroll
        for (int j = 0; j < 4; j++)
            g_ctx[((size_t)b * S_ + s) * H_ + h * HD_ + tn*4 + j] = acc[i][j];
    }
}

// ===========================================================================
// Host orchestration
// ===========================================================================
extern "C" void kernel_launch(void* const* d_in, const int* in_sizes, int n_in,
                              void* d_out, int out_size)
{
    const int*   tok   = (const int*)  d_in[0];
    const float* enc   = (const float*)d_in[1];
    const int*   mask  = (const int*)  d_in[2];
    const float* emb   = (const float*)d_in[3];
    const float* W_ih  = (const float*)d_in[4];
    const float* W_hh  = (const float*)d_in[5];
    const float* b_ih  = (const float*)d_in[6];
    const float* b_hh  = (const float*)d_in[7];
    const float* Wq    = (const float*)d_in[8];
    const float* bq    = (const float*)d_in[9];
    const float* Wk    = (const float*)d_in[10];
    const float* bk    = (const float*)d_in[11];
    const float* Wv    = (const float*)d_in[12];
    const float* bv    = (const float*)d_in[13];
    const float* Wo    = (const float*)d_in[14];
    const float* bo    = (const float*)d_in[15];
    const float* h0    = (const float*)d_in[16];
    const float* c0    = (const float*)d_in[17];
    float* out = (float*)d_out;

    float *p_xg, *p_K, *p_V, *p_H, *p_Q, *p_ctx, *p_outs;
    cudaGetSymbolAddress((void**)&p_xg,   g_xg);
    cudaGetSymbolAddress((void**)&p_K,    g_K);
    cudaGetSymbolAddress((void**)&p_V,    g_V);
    cudaGetSymbolAddress((void**)&p_H,    g_H);
    cudaGetSymbolAddress((void**)&p_Q,    g_Q);
    cudaGetSymbolAddress((void**)&p_ctx,  g_ctx);
    cudaGetSymbolAddress((void**)&p_outs, g_outs);

    __nv_bfloat16 *p_ehi, *p_elo, *p_ohi, *p_olo, *p_echi, *p_eclo;
    __nv_bfloat16 *p_wihhi, *p_wihlo, *p_wqhi, *p_wqlo, *p_wkhi, *p_wklo;
    __nv_bfloat16 *p_wvhi, *p_wvlo, *p_wohi, *p_wolo;
    __nv_bfloat16 *p_Hhi, *p_Hlo, *p_cxhi, *p_cxlo;
    cudaGetSymbolAddress((void**)&p_ehi,   g_embhi);
    cudaGetSymbolAddress((void**)&p_elo,   g_emblo);
    cudaGetSymbolAddress((void**)&p_ohi,   g_outhi);
    cudaGetSymbolAddress((void**)&p_olo,   g_outlo);
    cudaGetSymbolAddress((void**)&p_echi,  g_enchi);
    cudaGetSymbolAddress((void**)&p_eclo,  g_enclo);
    cudaGetSymbolAddress((void**)&p_wihhi, g_wihhi);
    cudaGetSymbolAddress((void**)&p_wihlo, g_wihlo);
    cudaGetSymbolAddress((void**)&p_wqhi,  g_wqhi);
    cudaGetSymbolAddress((void**)&p_wqlo,  g_wqlo);
    cudaGetSymbolAddress((void**)&p_wkhi,  g_wkhi);
    cudaGetSymbolAddress((void**)&p_wklo,  g_wklo);
    cudaGetSymbolAddress((void**)&p_wvhi,  g_wvhi);
    cudaGetSymbolAddress((void**)&p_wvlo,  g_wvlo);
    cudaGetSymbolAddress((void**)&p_wohi,  g_wohi);
    cudaGetSymbolAddress((void**)&p_wolo,  g_wolo);
    cudaGetSymbolAddress((void**)&p_Hhi,   g_Hhi);
    cudaGetSymbolAddress((void**)&p_Hlo,   g_Hlo);
    cudaGetSymbolAddress((void**)&p_cxhi,  g_ctxhi);
    cudaGetSymbolAddress((void**)&p_cxlo,  g_ctxlo);

    cudaFuncSetAttribute(hgemm_tn_mma,
                         cudaFuncAttributeMaxDynamicSharedMemorySize, LGS_SMEM);

    reset_k<<<1, 32>>>();

    // ---- operand splits (inputs; independent of compute order) ----
    split_bf16_k<<<(V_*H_/4 + 255)/256, 256>>>(emb,  p_ehi,   p_elo,   V_*H_/4);
    split_bf16_k<<<(BKV_*H_/4 + 255)/256, 256>>>(enc, p_echi, p_eclo, BKV_*H_/4);
    split_bf16_k<<<(G4_*H_/4 + 255)/256, 256>>>(W_ih, p_wihhi, p_wihlo, G4_*H_/4);
    split_bf16_k<<<(H_*H_/4 + 255)/256, 256>>>(Wq,   p_wqhi,  p_wqlo,  H_*H_/4);
    split_bf16_k<<<(H_*H_/4 + 255)/256, 256>>>(Wk,   p_wkhi,  p_wklo,  H_*H_/4);
    split_bf16_k<<<(H_*H_/4 + 255)/256, 256>>>(Wv,   p_wvhi,  p_wvlo,  H_*H_/4);
    split_bf16_k<<<(H_*H_/4 + 255)/256, 256>>>(Wo,   p_wohi,  p_wolo,  H_*H_/4);

    // ---- x-gates with fused embedding gather: [2048,2048] ----
    hgemm_tn_mma<<<dim3(BT_/128, G4_/128), 256, LGS_SMEM>>>(
        G4_, p_ehi, p_elo, tok, p_wihhi, p_wihlo, b_ih, b_hh, p_xg);
    // ---- encoder K/V projections: [8192,512] ----
    hgemm_tn_mma<<<dim3(BKV_/128, H_/128), 256, LGS_SMEM>>>(
        H_, p_echi, p_eclo, nullptr, p_wkhi, p_wklo, bk, nullptr, p_K);
    hgemm_tn_mma<<<dim3(BKV_/128, H_/128), 256, LGS_SMEM>>>(
        H_, p_echi, p_eclo, nullptr, p_wvhi, p_wvlo, bv, nullptr, p_V);

    // ---- serial LSTM recurrence -> g_H ----
    rnn_kernel<<<128, 256>>>(W_hh, h0, c0);

    // ---- Q projection from hidden history ----
    split_bf16_k<<<(BT_*H_/4 + 255)/256, 256>>>(p_H, p_Hhi, p_Hlo, BT_*H_/4);
    hgemm_tn_mma<<<dim3(BT_/128, H_/128), 256, LGS_SMEM>>>(
        H_, p_Hhi, p_Hlo, nullptr, p_wqhi, p_wqlo, bq, nullptr, p_Q);

    // ---- attention ----
    attn_scores_k<<<dim3(SKV_/64, S_/64, B_*NH_), 256>>>(mask);
    softmax_k<<<B_*NH_*S_, 128>>>();
    attn_ctx_k<<<dim3(S_/64, B_*NH_), 256>>>();

    // ---- output projection ----
    split_bf16_k<<<(BT_*H_/4 + 255)/256, 256>>>(p_ctx, p_cxhi, p_cxlo, BT_*H_/4);
    hgemm_tn_mma<<<dim3(BT_/128, H_/128), 256, LGS_SMEM>>>(
        H_, p_cxhi, p_cxlo, nullptr, p_wohi, p_wolo, bo, nullptr, p_outs);

    // ---- tied logits ----
    split_bf16_k<<<(BT_*H_/4 + 255)/256, 256>>>(p_outs, p_ohi, p_olo, BT_*H_/4);
    hgemm_tn_mma<<<dim3(BT_/128, V_/128), 256, LGS_SMEM>>>(
        V_, p_ohi, p_olo, nullptr, p_ehi, p_elo, nullptr, nullptr, out);
}

// round 11
// speedup vs baseline: 1.4266x; 1.0150x over previous
#include <cuda_runtime.h>
#include <cuda_bf16.h>
#include <math.h>
#include <cstdint>

// ---------------- problem constants ----------------
#define B_    8
#define S_    256
#define SKV_  1024
#define H_    512
#define NH_   8
#define HD_   64
#define G4_   2048            // 4*H
#define V_    32000
#define BT_   (B_*S_)         // 2048
#define BKV_  (B_*SKV_)       // 8192
#define K_GEMM 512            // shared K dim of every dense GEMM here

// ---------------- device scratch (static; allocation is forbidden) --------
__device__ float    g_xg  [BT_  * (size_t)G4_];
__device__ float    g_K   [BKV_ * (size_t)H_];
__device__ float    g_V   [BKV_ * (size_t)H_];
__device__ float    g_H   [BT_  * (size_t)H_];
__device__ float    g_Q   [BT_  * (size_t)H_];
__device__ float    g_ctx [BT_  * (size_t)H_];
__device__ float    g_outs[BT_  * (size_t)H_];
__device__ float    g_hcur[B_ * H_];
__device__ float    g_att [(size_t)B_ * NH_ * S_ * SKV_];
__device__ unsigned g_arrive[4];
// split-bf16 operand buffers
__device__ __nv_bfloat16 g_embhi[(size_t)V_ * H_];
__device__ __nv_bfloat16 g_emblo[(size_t)V_ * H_];
__device__ __nv_bfloat16 g_outhi[(size_t)BT_ * H_];
__device__ __nv_bfloat16 g_outlo[(size_t)BT_ * H_];
__device__ __nv_bfloat16 g_enchi[(size_t)BKV_ * H_];
__device__ __nv_bfloat16 g_enclo[(size_t)BKV_ * H_];
__device__ __nv_bfloat16 g_wihhi[(size_t)G4_ * H_];
__device__ __nv_bfloat16 g_wihlo[(size_t)G4_ * H_];
__device__ __nv_bfloat16 g_wqhi[(size_t)H_ * H_];
__device__ __nv_bfloat16 g_wqlo[(size_t)H_ * H_];
__device__ __nv_bfloat16 g_wkhi[(size_t)H_ * H_];
__device__ __nv_bfloat16 g_wklo[(size_t)H_ * H_];
__device__ __nv_bfloat16 g_wvhi[(size_t)H_ * H_];
__device__ __nv_bfloat16 g_wvlo[(size_t)H_ * H_];
__device__ __nv_bfloat16 g_wohi[(size_t)H_ * H_];
__device__ __nv_bfloat16 g_wolo[(size_t)H_ * H_];
__device__ __nv_bfloat16 g_Hhi [(size_t)BT_ * H_];
__device__ __nv_bfloat16 g_Hlo [(size_t)BT_ * H_];
__device__ __nv_bfloat16 g_ctxhi[(size_t)BT_ * H_];
__device__ __nv_bfloat16 g_ctxlo[(size_t)BT_ * H_];

// ---------------- async-copy / ldmatrix helpers ----------------
#define CP_ASYNC16(dst, src) \
    asm volatile("cp.async.cg.shared.global [%0], [%1], 16;" :: "r"(dst), "l"(src))
#define CP_COMMIT() asm volatile("cp.async.commit_group;" ::: "memory")
#define CP_WAIT0()  asm volatile("cp.async.wait_group 0;" ::: "memory")
#define CP_WAIT1()  asm volatile("cp.async.wait_group 1;" ::: "memory")
#define CP_WAIT2()  asm volatile("cp.async.wait_group 2;" ::: "memory")

__device__ __forceinline__ uint32_t smem_u32(const void* p) {
    uint32_t a;
    asm("{ .reg .u64 t; cvta.to.shared.u64 t, %1; cvt.u32.u64 %0, t; }"
        : "=r"(a) : "l"(p));
    return a;
}
#define LDMATRIX_X4(r0, r1, r2, r3, addr) \
    asm volatile("ldmatrix.sync.aligned.m8n8.x4.shared.b16 {%0,%1,%2,%3}, [%4];" \
        : "=r"(r0), "=r"(r1), "=r"(r2), "=r"(r3) : "r"(addr))

// ===========================================================================
// fp32 -> (bf16 hi, bf16 lo) split
// ===========================================================================
__global__ void __launch_bounds__(256) split_bf16_k(
    const float* __restrict__ x, __nv_bfloat16* __restrict__ hi,
    __nv_bfloat16* __restrict__ lo, int n4)
{
    int i = blockIdx.x * 256 + threadIdx.x;
    if (i >= n4) return;
    float4 v = ((const float4*)x)[i];
    __nv_bfloat16 h0 = __float2bfloat16(v.x), h1 = __float2bfloat16(v.y);
    __nv_bfloat16 h2 = __float2bfloat16(v.z), h3 = __float2bfloat16(v.w);
    __nv_bfloat16 l0 = __float2bfloat16(v.x - __bfloat162float(h0));
    __nv_bfloat16 l1 = __float2bfloat16(v.y - __bfloat162float(h1));
    __nv_bfloat16 l2 = __float2bfloat16(v.z - __bfloat162float(h2));
    __nv_bfloat16 l3 = __float2bfloat16(v.w - __bfloat162float(h3));
    __nv_bfloat162* hp = (__nv_bfloat162*)(hi + (size_t)i * 4);
    __nv_bfloat162* lp = (__nv_bfloat162*)(lo + (size_t)i * 4);
    hp[0] = __nv_bfloat162(h0, h1); hp[1] = __nv_bfloat162(h2, h3);
    lp[0] = __nv_bfloat162(l0, l1); lp[1] = __nv_bfloat162(l2, l3);
}

// ===========================================================================
// Split-bf16 TN GEMM (3-product): C[m][n] = sum_k A'[m][k]*B[n][k] (+bias)
//   4-stage cp.async ring, ONE __syncthreads per K-slab.
//   mma.sync m16n8k16 bf16 + ldmatrix. CTA tile 128x128, 8 warps (4m x 2n).
//   K fixed 512 -> 48 slabs (3 split segments x 16).
//   Dynamic smem: 4 x 20480 = 81920 B; 2 CTAs/SM.
// ===========================================================================
#define LGS_STAGE  20480
#define LGS_BOFF   10240
#define LGS_STAGES 4
#define LGS_SMEM   (LGS_STAGES * LGS_STAGE)   // 81920

__global__ void __launch_bounds__(256, 2) hgemm_tn_mma(
    int ldc,
    const __nv_bfloat16* __restrict__ Ahi, const __nv_bfloat16* __restrict__ Alo,
    const int* __restrict__ gidx,
    const __nv_bfloat16* __restrict__ Bhi, const __nv_bfloat16* __restrict__ Blo,
    const float* __restrict__ bias1, const float* __restrict__ bias2,
    float* __restrict__ C)
{
    extern __shared__ char smem[];
    const uint32_t sbase = smem_u32(smem);
    const int tid  = threadIdx.x;
    const int lane = tid & 31;
    const int warp = tid >> 5;
    const int wm   = warp >> 1, wn = warp & 1;
    const int g    = lane >> 2, t4 = lane & 3;
    const int m0   = blockIdx.x * 128;
    const int n0   = blockIdx.y * 128;

    float acc[2][8][4];
#pragma unroll
    for (int mi = 0; mi < 2; mi++)
#pragma unroll
        for (int ni = 0; ni < 8; ni++)
#pragma unroll
            for (int f = 0; f < 4; f++) acc[mi][ni][f] = 0.f;

    // per-thread cp.async chunk mapping (row indices are loop-invariant)
    const int c0r = (tid)       >> 2, c0k = ((tid)       & 3) * 8;
    const int c1r = (tid + 256) >> 2, c1k = ((tid + 256) & 3) * 8;
    int ar0 = m0 + c0r, ar1 = m0 + c1r;
    if (gidx) { ar0 = gidx[ar0]; ar1 = gidx[ar1]; }
    const int br0 = n0 + c0r, br1 = n0 + c1r;

    const int lm_row = lane & 15;
    const int lm_col = (lane >> 4) * 16;

    auto issue = [&](int t, int buf) {
        const int seg  = t >> 4;
        const int kofs = (t & 15) * 32;
        const __nv_bfloat16* Ap = (seg < 2)  ? Ahi : Alo;
        const __nv_bfloat16* Bp = (seg == 1) ? Blo : Bhi;
        const uint32_t sA = sbase + buf * LGS_STAGE;
        const uint32_t sB = sA + LGS_BOFF;
        CP_ASYNC16(sA + c0r * 80 + c0k * 2, Ap + (size_t)ar0 * K_GEMM + kofs + c0k);
        CP_ASYNC16(sA + c1r * 80 + c1k * 2, Ap + (size_t)ar1 * K_GEMM + kofs + c1k);
        CP_ASYNC16(sB + c0r * 80 + c0k * 2, Bp + (size_t)br0 * K_GEMM + kofs + c0k);
        CP_ASYNC16(sB + c1r * 80 + c1k * 2, Bp + (size_t)br1 * K_GEMM + kofs + c1k);
    };

    // prologue: stages 0..2 in flight
    issue(0, 0); CP_COMMIT();
    issue(1, 1); CP_COMMIT();
    issue(2, 2); CP_COMMIT();

    for (int t = 0; t < 48; t++) {
        // stage-t data guaranteed complete (pending <= {t, t+1, t+2})
        if (t < 46)       { CP_WAIT2(); }
        else if (t == 46) { CP_WAIT1(); }
        else              { CP_WAIT0(); }
        __syncthreads();   // (a) all threads' stage-t copies visible
                           // (b) all warps done consuming stage t-1 -> safe
                           //     to overwrite its buffer below
        if (t + 3 < 48) { issue(t + 3, (t + 3) & 3); CP_COMMIT(); }

        const uint32_t sA = sbase + (t & 3) * LGS_STAGE;
        const uint32_t sB = sA + LGS_BOFF;

#pragma unroll
        for (int k0 = 0; k0 < 2; k0++) {
            const uint32_t kb = k0 * 32 + lm_col;
            uint32_t a[2][4];
#pragma unroll
            for (int mi = 0; mi < 2; mi++) {
                uint32_t addr = sA + (uint32_t)(wm * 32 + mi * 16 + lm_row) * 80 + kb;
                LDMATRIX_X4(a[mi][0], a[mi][1], a[mi][2], a[mi][3], addr);
            }
            uint32_t bf[4][4];
#pragma unroll
            for (int nj = 0; nj < 4; nj++) {
                uint32_t addr = sB + (uint32_t)(wn * 64 + nj * 16 + lm_row) * 80 + kb;
                LDMATRIX_X4(bf[nj][0], bf[nj][1], bf[nj][2], bf[nj][3], addr);
            }
#pragma unroll
            for (int nj = 0; nj < 4; nj++) {
#pragma unroll
                for (int hh = 0; hh < 2; hh++) {
                    const int ni = nj * 2 + hh;
                    uint32_t b0 = bf[nj][hh], b1 = bf[nj][hh + 2];
#pragma unroll
                    for (int mi = 0; mi < 2; mi++) {
                        asm volatile(
                            "mma.sync.aligned.m16n8k16.row.col.f32.bf16.bf16.f32 "
                            "{%0,%1,%2,%3}, {%4,%5,%6,%7}, {%8,%9}, {%0,%1,%2,%3};\n"
                            : "+f"(acc[mi][ni][0]), "+f"(acc[mi][ni][1]),
                              "+f"(acc[mi][ni][2]), "+f"(acc[mi][ni][3])
                            : "r"(a[mi][0]), "r"(a[mi][1]), "r"(a[mi][2]), "r"(a[mi][3]),
                              "r"(b0), "r"(b1));
                    }
                }
            }
        }
    }

#pragma unroll
    for (int mi = 0; mi < 2; mi++) {
#pragma unroll
        for (int ni = 0; ni < 8; ni++) {
            int row = m0 + wm * 32 + mi * 16 + g;
            int col = n0 + wn * 64 + ni * 8 + 2 * t4;
            float b0 = 0.f, b1 = 0.f;
            if (bias1) { b0 = bias1[col]; b1 = bias1[col + 1]; }
            if (bias2) { b0 += bias2[col]; b1 += bias2[col + 1]; }
            float2 v0 = make_float2(acc[mi][ni][0] + b0, acc[mi][ni][1] + b1);
            float2 v1 = make_float2(acc[mi][ni][2] + b0, acc[mi][ni][3] + b1);
            *(float2*)&C[(size_t)row * ldc + col]       = v0;
            *(float2*)&C[(size_t)(row + 8) * ldc + col] = v1;
        }
    }
}

// ===========================================================================
// Reset kernel
// ===========================================================================
__global__ void reset_k()
{
    if (threadIdx.x < 4) g_arrive[threadIdx.x] = 0u;
}

// ===========================================================================
// Persistent LSTM recurrence (unchanged, passing)
// ===========================================================================
__device__ __forceinline__ float sigm(float x) { return 1.f / (1.f + expf(-x)); }

__global__ void __launch_bounds__(256, 1) rnn_kernel(
    const float* __restrict__ W_hh, const float* __restrict__ h0,
    const float* __restrict__ c0)
{
    const int cta  = blockIdx.x;
    const int pair = cta >> 5;
    const int grp  = cta & 31;
    const int tid  = threadIdx.x;
    const int q    = tid >> 6;
    const int r    = tid & 63;
    const int gate = r >> 4, uu = r & 15;
    const int unit = grp * 16 + uu;

    __shared__ float h_sm[2][H_];
    __shared__ float red[4][64][2];
    __shared__ float gsm[64][2];
    __shared__ float c_sm[2][16];

    float w[128];
    {
        const float4* wp = (const float4*)(W_hh + (size_t)(gate * H_ + unit) * H_ + q * 128);
#pragma unroll
        for (int j = 0; j < 32; j++) {
            float4 v = wp[j];
            w[4*j+0] = v.x; w[4*j+1] = v.y; w[4*j+2] = v.z; w[4*j+3] = v.w;
        }
    }

    for (int s = 0; s < S_; s++) {
        {
            const int bb = tid >> 7, off = (tid & 127) * 4;
            float4 v;
            if (s == 0) v = *(const float4*)(h0 + (size_t)(pair*2 + bb) * H_ + off);
            else        v = __ldcg((const float4*)(g_hcur + (size_t)(pair*2 + bb) * H_ + off));
            *(float4*)&h_sm[bb][off] = v;
        }
        if (s == 0 && tid < 32) {
            int b2 = tid >> 4, u2 = tid & 15;
            c_sm[b2][u2] = c0[(size_t)(pair*2 + b2) * H_ + grp*16 + u2];
        }
        __syncthreads();

        float a0 = 0.f, a1 = 0.f;
        {
            const float* hp0 = &h_sm[0][q * 128];
            const float* hp1 = &h_sm[1][q * 128];
#pragma unroll
            for (int j = 0; j < 128; j++) {
                a0 += w[j] * hp0[j];
                a1 += w[j] * hp1[j];
            }
        }
        red[q][r][0] = a0;
        red[q][r][1] = a1;
        __syncthreads();

        if (tid < 128) {
            const int rr = tid >> 1, bb = tid & 1;
            const int gg = rr >> 4, u2 = rr & 15;
            float g = red[0][rr][bb] + red[1][rr][bb] + red[2][rr][bb] + red[3][rr][bb]
                    + g_xg[((size_t)(pair*2 + bb) * S_ + s) * G4_ + gg * H_ + grp*16 + u2];
            gsm[rr][bb] = g;
        }
        __syncthreads();

        if (tid < 32) {
            const int bb = tid >> 4, u2 = tid & 15;
            float iv = gsm[ 0 + u2][bb];
            float fv = gsm[16 + u2][bb];
            float gv = gsm[32 + u2][bb];
            float ov = gsm[48 + u2][bb];
            float cn = sigm(fv) * c_sm[bb][u2] + sigm(iv) * tanhf(gv);
            float hn = sigm(ov) * tanhf(cn);
            c_sm[bb][u2] = cn;
            const int bg = pair*2 + bb, un = grp*16 + u2;
            g_hcur[(size_t)bg * H_ + un] = hn;
            g_H[((size_t)bg * S_ + s) * H_ + un] = hn;
            __threadfence();
        }
        __syncthreads();

        if (tid == 0) {
            atomicAdd(&g_arrive[pair], 1u);
            const unsigned target = 32u * (unsigned)(s + 1);
            while (*((volatile unsigned*)&g_arrive[pair]) < target) { }
        }
        __syncthreads();
        __threadfence();
    }
}

// ===========================================================================
// Attention scores (unchanged)
// ===========================================================================
__global__ void __launch_bounds__(256) attn_scores_k(const int* __restrict__ mask)
{
    __shared__ float Qs[64][65];
    __shared__ float Ks[64][65];
    const int bh = blockIdx.z, b = bh >> 3, h = bh & 7;
    const int s0 = blockIdx.y * 64, k0 = blockIdx.x * 64;
    const int tid = threadIdx.x;

    for (int e = tid; e < 64 * 64; e += 256) {
        int row = e >> 6, col = e & 63;
        Qs[row][col] = g_Q[((size_t)b * S_ + s0 + row) * H_ + h * HD_ + col];
        Ks[row][col] = g_K[((size_t)b * SKV_ + k0 + row) * H_ + h * HD_ + col];
    }
    __syncthreads();

    const int tm = tid >> 4, tn = tid & 15;
    float acc[4][4];
#pragma unroll
    for (int i = 0; i < 4; i++)
#pragma unroll
        for (int j = 0; j < 4; j++) acc[i][j] = 0.f;

#pragma unroll 8
    for (int d = 0; d < 64; d++) {
        float a[4], bb[4];
#pragma unroll
        for (int i = 0; i < 4; i++) a[i]  = Qs[tm*4 + i][d];
#pragma unroll
        for (int j = 0; j < 4; j++) bb[j] = Ks[tn*4 + j][d];
#pragma unroll
        for (int i = 0; i < 4; i++)
#pragma unroll
            for (int j = 0; j < 4; j++) acc[i][j] += a[i] * bb[j];
    }

    const float scale = 0.125f;
#pragma unroll
    for (int i = 0; i < 4; i++) {
        int s = s0 + tm*4 + i;
#pragma unroll
        for (int j = 0; j < 4; j++) {
            int k = k0 + tn*4 + j;
            float v = acc[i][j] * scale;
            if (mask[b * SKV_ + k] != 1) v = -1e9f;
            g_att[((size_t)bh * S_ + s) * SKV_ + k] = v;
        }
    }
}

// ===========================================================================
// Softmax (unchanged)
// ===========================================================================
__global__ void __launch_bounds__(128) softmax_k()
{
    const size_t base = (size_t)blockIdx.x * SKV_;
    const int tid = threadIdx.x;
    float v[8];
    float mx = -1e30f;
#pragma unroll
    for (int i = 0; i < 8; i++) {
        v[i] = g_att[base + tid + i * 128];
        mx = fmaxf(mx, v[i]);
    }
    __shared__ float sm[4];
#pragma unroll
    for (int off = 16; off > 0; off >>= 1)
        mx = fmaxf(mx, __shfl_xor_sync(0xffffffffu, mx, off));
    if ((tid & 31) == 0) sm[tid >> 5] = mx;
    __syncthreads();
    mx = fmaxf(fmaxf(sm[0], sm[1]), fmaxf(sm[2], sm[3]));

    float sum = 0.f;
#pragma unroll
    for (int i = 0; i < 8; i++) { v[i] = expf(v[i] - mx); sum += v[i]; }
#pragma unroll
    for (int off = 16; off > 0; off >>= 1)
        sum += __shfl_xor_sync(0xffffffffu, sum, off);
    __syncthreads();
    if ((tid & 31) == 0) sm[tid >> 5] = sum;
    __syncthreads();
    sum = sm[0] + sm[1] + sm[2] + sm[3];
    const float inv = 1.f / sum;
#pragma unroll
    for (int i = 0; i < 8; i++) g_att[base + tid + i * 128] = v[i] * inv;
}

// ===========================================================================
// attn @ V (unchanged)
// ===========================================================================
__global__ void __launch_bounds__(256) attn_ctx_k()
{
    __shared__ float As[64][65];
    __shared__ float Vs[64][65];
    const int bh = blockIdx.y, b = bh >> 3, h = bh & 7;
    const int s0 = blockIdx.x * 64;
    const int tid = threadIdx.x;
    const int tm = tid >> 4, tn = tid & 15;

    float acc[4][4];
#pragma unroll
    for (int i = 0; i < 4; i++)
#pragma unroll
        for (int j = 0; j < 4; j++) acc[i][j] = 0.f;

    for (int kt = 0; kt < SKV_; kt += 64) {
        for (int e = tid; e < 64 * 64; e += 256) {
            int row = e >> 6, col = e & 63;
            As[row][col] = g_att[((size_t)bh * S_ + s0 + row) * SKV_ + kt + col];
            Vs[row][col] = g_V[((size_t)b * SKV_ + kt + row) * H_ + h * HD_ + col];
        }
        __syncthreads();
#pragma unroll 8
        for (int kk = 0; kk < 64; kk++) {
            float a[4], vv[4];
#pragma unroll
            for (int i = 0; i < 4; i++) a[i]  = As[tm*4 + i][kk];
#pragma unroll
            for (int j = 0; j < 4; j++) vv[j] = Vs[kk][tn*4 + j];
#pragma unroll
            for (int i = 0; i < 4; i++)
#pragma unroll
                for (int j = 0; j < 4; j++) acc[i][j] += a[i] * vv[j];
        }
        __syncthreads();
    }

#pragma unroll
    for (int i = 0; i < 4; i++) {
        int s = s0 + tm*4 + i;
#pragma unroll
        for (int j = 0; j < 4; j++)
            g_ctx[((size_t)b * S_ + s) * H_ + h * HD_ + tn*4 + j] = acc[i][j];
    }
}

// ===========================================================================
// Host orchestration
// ===========================================================================
extern "C" void kernel_launch(void* const* d_in, const int* in_sizes, int n_in,
                              void* d_out, int out_size)
{
    const int*   tok   = (const int*)  d_in[0];
    const float* enc   = (const float*)d_in[1];
    const int*   mask  = (const int*)  d_in[2];
    const float* emb   = (const float*)d_in[3];
    const float* W_ih  = (const float*)d_in[4];
    const float* W_hh  = (const float*)d_in[5];
    const float* b_ih  = (const float*)d_in[6];
    const float* b_hh  = (const float*)d_in[7];
    const float* Wq    = (const float*)d_in[8];
    const float* bq    = (const float*)d_in[9];
    const float* Wk    = (const float*)d_in[10];
    const float* bk    = (const float*)d_in[11];
    const float* Wv    = (const float*)d_in[12];
    const float* bv    = (const float*)d_in[13];
    const float* Wo    = (const float*)d_in[14];
    const float* bo    = (const float*)d_in[15];
    const float* h0    = (const float*)d_in[16];
    const float* c0    = (const float*)d_in[17];
    float* out = (float*)d_out;

    float *p_xg, *p_K, *p_V, *p_H, *p_Q, *p_ctx, *p_outs;
    cudaGetSymbolAddress((void**)&p_xg,   g_xg);
    cudaGetSymbolAddress((void**)&p_K,    g_K);
    cudaGetSymbolAddress((void**)&p_V,    g_V);
    cudaGetSymbolAddress((void**)&p_H,    g_H);
    cudaGetSymbolAddress((void**)&p_Q,    g_Q);
    cudaGetSymbolAddress((void**)&p_ctx,  g_ctx);
    cudaGetSymbolAddress((void**)&p_outs, g_outs);

    __nv_bfloat16 *p_ehi, *p_elo, *p_ohi, *p_olo, *p_echi, *p_eclo;
    __nv_bfloat16 *p_wihhi, *p_wihlo, *p_wqhi, *p_wqlo, *p_wkhi, *p_wklo;
    __nv_bfloat16 *p_wvhi, *p_wvlo, *p_wohi, *p_wolo;
    __nv_bfloat16 *p_Hhi, *p_Hlo, *p_cxhi, *p_cxlo;
    cudaGetSymbolAddress((void**)&p_ehi,   g_embhi);
    cudaGetSymbolAddress((void**)&p_elo,   g_emblo);
    cudaGetSymbolAddress((void**)&p_ohi,   g_outhi);
    cudaGetSymbolAddress((void**)&p_olo,   g_outlo);
    cudaGetSymbolAddress((void**)&p_echi,  g_enchi);
    cudaGetSymbolAddress((void**)&p_eclo,  g_enclo);
    cudaGetSymbolAddress((void**)&p_wihhi, g_wihhi);
    cudaGetSymbolAddress((void**)&p_wihlo, g_wihlo);
    cudaGetSymbolAddress((void**)&p_wqhi,  g_wqhi);
    cudaGetSymbolAddress((void**)&p_wqlo,  g_wqlo);
    cudaGetSymbolAddress((void**)&p_wkhi,  g_wkhi);
    cudaGetSymbolAddress((void**)&p_wklo,  g_wklo);
    cudaGetSymbolAddress((void**)&p_wvhi,  g_wvhi);
    cudaGetSymbolAddress((void**)&p_wvlo,  g_wvlo);
    cudaGetSymbolAddress((void**)&p_wohi,  g_wohi);
    cudaGetSymbolAddress((void**)&p_wolo,  g_wolo);
    cudaGetSymbolAddress((void**)&p_Hhi,   g_Hhi);
    cudaGetSymbolAddress((void**)&p_Hlo,   g_Hlo);
    cudaGetSymbolAddress((void**)&p_cxhi,  g_ctxhi);
    cudaGetSymbolAddress((void**)&p_cxlo,  g_ctxlo);

    cudaFuncSetAttribute(hgemm_tn_mma,
                         cudaFuncAttributeMaxDynamicSharedMemorySize, LGS_SMEM);

    reset_k<<<1, 32>>>();

    // ---- operand splits (inputs; independent of compute order) ----
    split_bf16_k<<<(V_*H_/4 + 255)/256, 256>>>(emb,  p_ehi,   p_elo,   V_*H_/4);
    split_bf16_k<<<(BKV_*H_/4 + 255)/256, 256>>>(enc, p_echi, p_eclo, BKV_*H_/4);
    split_bf16_k<<<(G4_*H_/4 + 255)/256, 256>>>(W_ih, p_wihhi, p_wihlo, G4_*H_/4);
    split_bf16_k<<<(H_*H_/4 + 255)/256, 256>>>(Wq,   p_wqhi,  p_wqlo,  H_*H_/4);
    split_bf16_k<<<(H_*H_/4 + 255)/256, 256>>>(Wk,   p_wkhi,  p_wklo,  H_*H_/4);
    split_bf16_k<<<(H_*H_/4 + 255)/256, 256>>>(Wv,   p_wvhi,  p_wvlo,  H_*H_/4);
    split_bf16_k<<<(H_*H_/4 + 255)/256, 256>>>(Wo,   p_wohi,  p_wolo,  H_*H_/4);

    // ---- x-gates with fused embedding gather: [2048,2048] ----
    hgemm_tn_mma<<<dim3(BT_/128, G4_/128), 256, LGS_SMEM>>>(
        G4_, p_ehi, p_elo, tok, p_wihhi, p_wihlo, b_ih, b_hh, p_xg);
    // ---- encoder K/V projections: [8192,512] ----
    hgemm_tn_mma<<<dim3(BKV_/128, H_/128), 256, LGS_SMEM>>>(
        H_, p_echi, p_eclo, nullptr, p_wkhi, p_wklo, bk, nullptr, p_K);
    hgemm_tn_mma<<<dim3(BKV_/128, H_/128), 256, LGS_SMEM>>>(
        H_, p_echi, p_eclo, nullptr, p_wvhi, p_wvlo, bv, nullptr, p_V);

    // ---- serial LSTM recurrence -> g_H ----
    rnn_kernel<<<128, 256>>>(W_hh, h0, c0);

    // ---- Q projection from hidden history ----
    split_bf16_k<<<(BT_*H_/4 + 255)/256, 256>>>(p_H, p_Hhi, p_Hlo, BT_*H_/4);
    hgemm_tn_mma<<<dim3(BT_/128, H_/128), 256, LGS_SMEM>>>(
        H_, p_Hhi, p_Hlo, nullptr, p_wqhi, p_wqlo, bq, nullptr, p_Q);

    // ---- attention ----
    attn_scores_k<<<dim3(SKV_/64, S_/64, B_*NH_), 256>>>(mask);
    softmax_k<<<B_*NH_*S_, 128>>>();
    attn_ctx_k<<<dim3(S_/64, B_*NH_), 256>>>();

    // ---- output projection ----
    split_bf16_k<<<(BT_*H_/4 + 255)/256, 256>>>(p_ctx, p_cxhi, p_cxlo, BT_*H_/4);
    hgemm_tn_mma<<<dim3(BT_/128, H_/128), 256, LGS_SMEM>>>(
        H_, p_cxhi, p_cxlo, nullptr, p_wohi, p_wolo, bo, nullptr, p_outs);

    // ---- tied logits ----
    split_bf16_k<<<(BT_*H_/4 + 255)/256, 256>>>(p_outs, p_ohi, p_olo, BT_*H_/4);
    hgemm_tn_mma<<<dim3(BT_/128, V_/128), 256, LGS_SMEM>>>(
        V_, p_ohi, p_olo, nullptr, p_ehi, p_elo, nullptr, nullptr, out);
}

// round 12
// speedup vs baseline: 1.5228x; 1.0674x over previous
#include <cuda_runtime.h>
#include <cuda_bf16.h>
#include <math.h>
#include <cstdint>

// ---------------- problem constants ----------------
#define B_    8
#define S_    256
#define SKV_  1024
#define H_    512
#define NH_   8
#define HD_   64
#define G4_   2048
#define V_    32000
#define BT_   (B_*S_)         // 2048
#define BKV_  (B_*SKV_)       // 8192
#define K_GEMM 512

// ---------------- device scratch ----------------
__device__ float    g_xg  [BT_  * (size_t)G4_];
__device__ float    g_K   [BKV_ * (size_t)H_];
__device__ float    g_V   [BKV_ * (size_t)H_];
__device__ float    g_H   [BT_  * (size_t)H_];
__device__ float    g_Q   [BT_  * (size_t)H_];
__device__ float    g_ctx [BT_  * (size_t)H_];
__device__ float    g_outs[BT_  * (size_t)H_];
__device__ float    g_hcur[B_ * H_];
__device__ float    g_att [(size_t)B_ * NH_ * S_ * SKV_];
__device__ unsigned g_arrive[4];
// split-bf16 operand buffers
__device__ __nv_bfloat16 g_embhi[(size_t)V_ * H_];
__device__ __nv_bfloat16 g_emblo[(size_t)V_ * H_];
__device__ __nv_bfloat16 g_outhi[(size_t)BT_ * H_];
__device__ __nv_bfloat16 g_outlo[(size_t)BT_ * H_];
__device__ __nv_bfloat16 g_enchi[(size_t)BKV_ * H_];
__device__ __nv_bfloat16 g_enclo[(size_t)BKV_ * H_];
__device__ __nv_bfloat16 g_wihhi[(size_t)G4_ * H_];
__device__ __nv_bfloat16 g_wihlo[(size_t)G4_ * H_];
__device__ __nv_bfloat16 g_wqhi[(size_t)H_ * H_];
__device__ __nv_bfloat16 g_wqlo[(size_t)H_ * H_];
__device__ __nv_bfloat16 g_wkhi[(size_t)H_ * H_];
__device__ __nv_bfloat16 g_wklo[(size_t)H_ * H_];
__device__ __nv_bfloat16 g_wvhi[(size_t)H_ * H_];
__device__ __nv_bfloat16 g_wvlo[(size_t)H_ * H_];
__device__ __nv_bfloat16 g_wohi[(size_t)H_ * H_];
__device__ __nv_bfloat16 g_wolo[(size_t)H_ * H_];
__device__ __nv_bfloat16 g_Hhi [(size_t)BT_ * H_];
__device__ __nv_bfloat16 g_Hlo [(size_t)BT_ * H_];
__device__ __nv_bfloat16 g_ctxhi[(size_t)BT_ * H_];
__device__ __nv_bfloat16 g_ctxlo[(size_t)BT_ * H_];
// attention operands
__device__ __nv_bfloat16 g_Qhi [(size_t)BT_ * H_];
__device__ __nv_bfloat16 g_Qlo [(size_t)BT_ * H_];
__device__ __nv_bfloat16 g_Khi [(size_t)BKV_ * H_];
__device__ __nv_bfloat16 g_Klo [(size_t)BKV_ * H_];
__device__ __nv_bfloat16 g_atth[(size_t)B_ * NH_ * S_ * SKV_];
__device__ __nv_bfloat16 g_attl[(size_t)B_ * NH_ * S_ * SKV_];
__device__ __nv_bfloat16 g_VThi[(size_t)B_ * H_ * SKV_];
__device__ __nv_bfloat16 g_VTlo[(size_t)B_ * H_ * SKV_];

// ---------------- helpers ----------------
#define CP_ASYNC16(dst, src) \
    asm volatile("cp.async.cg.shared.global [%0], [%1], 16;" :: "r"(dst), "l"(src))
#define CP_COMMIT() asm volatile("cp.async.commit_group;" ::: "memory")
#define CP_WAIT0()  asm volatile("cp.async.wait_group 0;" ::: "memory")
#define CP_WAIT1()  asm volatile("cp.async.wait_group 1;" ::: "memory")
#define CP_WAIT2()  asm volatile("cp.async.wait_group 2;" ::: "memory")

__device__ __forceinline__ uint32_t smem_u32(const void* p) {
    uint32_t a;
    asm("{ .reg .u64 t; cvta.to.shared.u64 t, %1; cvt.u32.u64 %0, t; }"
        : "=r"(a) : "l"(p));
    return a;
}
#define LDMATRIX_X4(r0, r1, r2, r3, addr) \
    asm volatile("ldmatrix.sync.aligned.m8n8.x4.shared.b16 {%0,%1,%2,%3}, [%4];" \
        : "=r"(r0), "=r"(r1), "=r"(r2), "=r"(r3) : "r"(addr))
#define MMA16816(acc, a, b0v, b1v) \
    asm volatile( \
        "mma.sync.aligned.m16n8k16.row.col.f32.bf16.bf16.f32 " \
        "{%0,%1,%2,%3}, {%4,%5,%6,%7}, {%8,%9}, {%0,%1,%2,%3};\n" \
        : "+f"((acc)[0]), "+f"((acc)[1]), "+f"((acc)[2]), "+f"((acc)[3]) \
        : "r"((a)[0]), "r"((a)[1]), "r"((a)[2]), "r"((a)[3]), "r"(b0v), "r"(b1v))

__device__ __forceinline__ void split2(float v, __nv_bfloat16& h, __nv_bfloat16& l) {
    h = __float2bfloat16(v);
    l = __float2bfloat16(v - __bfloat162float(h));
}

// ===========================================================================
// fp32 -> (bf16 hi, bf16 lo) split; 4 independent float4 per thread (MLP=4)
// ===========================================================================
__global__ void __launch_bounds__(256) split_bf16_k(
    const float* __restrict__ x, __nv_bfloat16* __restrict__ hi,
    __nv_bfloat16* __restrict__ lo, int n4)
{
    int base = blockIdx.x * 1024 + threadIdx.x;
    float4 v[4];
    bool p[4];
#pragma unroll
    for (int j = 0; j < 4; j++) {
        int idx = base + j * 256;
        p[j] = idx < n4;
        if (p[j]) v[j] = ((const float4*)x)[idx];
    }
#pragma unroll
    for (int j = 0; j < 4; j++) {
        if (!p[j]) continue;
        int idx = base + j * 256;
        __nv_bfloat16 h0,h1,h2,h3,l0,l1,l2,l3;
        split2(v[j].x,h0,l0); split2(v[j].y,h1,l1);
        split2(v[j].z,h2,l2); split2(v[j].w,h3,l3);
        __nv_bfloat162* hp = (__nv_bfloat162*)(hi + (size_t)idx * 4);
        __nv_bfloat162* lp = (__nv_bfloat162*)(lo + (size_t)idx * 4);
        hp[0] = __nv_bfloat162(h0,h1); hp[1] = __nv_bfloat162(h2,h3);
        lp[0] = __nv_bfloat162(l0,l1); lp[1] = __nv_bfloat162(l2,l3);
    }
}

// ===========================================================================
// Dense split-bf16 TN GEMM (unchanged from passing R11)
// ===========================================================================
#define LGS_STAGE  20480
#define LGS_BOFF   10240
#define LGS_SMEM   (4 * LGS_STAGE)

__global__ void __launch_bounds__(256, 2) hgemm_tn_mma(
    int ldc,
    const __nv_bfloat16* __restrict__ Ahi, const __nv_bfloat16* __restrict__ Alo,
    const int* __restrict__ gidx,
    const __nv_bfloat16* __restrict__ Bhi, const __nv_bfloat16* __restrict__ Blo,
    const float* __restrict__ bias1, const float* __restrict__ bias2,
    float* __restrict__ C)
{
    extern __shared__ char smem[];
    const uint32_t sbase = smem_u32(smem);
    const int tid  = threadIdx.x;
    const int lane = tid & 31;
    const int warp = tid >> 5;
    const int wm   = warp >> 1, wn = warp & 1;
    const int g    = lane >> 2, t4 = lane & 3;
    const int m0   = blockIdx.x * 128;
    const int n0   = blockIdx.y * 128;

    float acc[2][8][4];
#pragma unroll
    for (int mi = 0; mi < 2; mi++)
#pragma unroll
        for (int ni = 0; ni < 8; ni++)
#pragma unroll
            for (int f = 0; f < 4; f++) acc[mi][ni][f] = 0.f;

    const int c0r = (tid)       >> 2, c0k = ((tid)       & 3) * 8;
    const int c1r = (tid + 256) >> 2, c1k = ((tid + 256) & 3) * 8;
    int ar0 = m0 + c0r, ar1 = m0 + c1r;
    if (gidx) { ar0 = gidx[ar0]; ar1 = gidx[ar1]; }
    const int br0 = n0 + c0r, br1 = n0 + c1r;

    const int lm_row = lane & 15;
    const int lm_col = (lane >> 4) * 16;

    auto issue = [&](int t, int buf) {
        const int seg  = t >> 4;
        const int kofs = (t & 15) * 32;
        const __nv_bfloat16* Ap = (seg < 2)  ? Ahi : Alo;
        const __nv_bfloat16* Bp = (seg == 1) ? Blo : Bhi;
        const uint32_t sA = sbase + buf * LGS_STAGE;
        const uint32_t sB = sA + LGS_BOFF;
        CP_ASYNC16(sA + c0r * 80 + c0k * 2, Ap + (size_t)ar0 * K_GEMM + kofs + c0k);
        CP_ASYNC16(sA + c1r * 80 + c1k * 2, Ap + (size_t)ar1 * K_GEMM + kofs + c1k);
        CP_ASYNC16(sB + c0r * 80 + c0k * 2, Bp + (size_t)br0 * K_GEMM + kofs + c0k);
        CP_ASYNC16(sB + c1r * 80 + c1k * 2, Bp + (size_t)br1 * K_GEMM + kofs + c1k);
    };

    issue(0, 0); CP_COMMIT();
    issue(1, 1); CP_COMMIT();
    issue(2, 2); CP_COMMIT();

    for (int t = 0; t < 48; t++) {
        if (t < 46)       { CP_WAIT2(); }
        else if (t == 46) { CP_WAIT1(); }
        else              { CP_WAIT0(); }
        __syncthreads();
        if (t + 3 < 48) { issue(t + 3, (t + 3) & 3); CP_COMMIT(); }

        const uint32_t sA = sbase + (t & 3) * LGS_STAGE;
        const uint32_t sB = sA + LGS_BOFF;

#pragma unroll
        for (int k0 = 0; k0 < 2; k0++) {
            const uint32_t kb = k0 * 32 + lm_col;
            uint32_t a[2][4];
#pragma unroll
            for (int mi = 0; mi < 2; mi++) {
                uint32_t addr = sA + (uint32_t)(wm * 32 + mi * 16 + lm_row) * 80 + kb;
                LDMATRIX_X4(a[mi][0], a[mi][1], a[mi][2], a[mi][3], addr);
            }
            uint32_t bf[4][4];
#pragma unroll
            for (int nj = 0; nj < 4; nj++) {
                uint32_t addr = sB + (uint32_t)(wn * 64 + nj * 16 + lm_row) * 80 + kb;
                LDMATRIX_X4(bf[nj][0], bf[nj][1], bf[nj][2], bf[nj][3], addr);
            }
#pragma unroll
            for (int nj = 0; nj < 4; nj++)
#pragma unroll
                for (int hh = 0; hh < 2; hh++) {
                    const int ni = nj * 2 + hh;
#pragma unroll
                    for (int mi = 0; mi < 2; mi++)
                        MMA16816(acc[mi][ni], a[mi], bf[nj][hh], bf[nj][hh + 2]);
                }
        }
    }

#pragma unroll
    for (int mi = 0; mi < 2; mi++)
#pragma unroll
        for (int ni = 0; ni < 8; ni++) {
            int row = m0 + wm * 32 + mi * 16 + g;
            int col = n0 + wn * 64 + ni * 8 + 2 * t4;
            float b0 = 0.f, b1 = 0.f;
            if (bias1) { b0 = bias1[col]; b1 = bias1[col + 1]; }
            if (bias2) { b0 += bias2[col]; b1 += bias2[col + 1]; }
            float2 v0 = make_float2(acc[mi][ni][0] + b0, acc[mi][ni][1] + b1);
            float2 v1 = make_float2(acc[mi][ni][2] + b0, acc[mi][ni][3] + b1);
            *(float2*)&C[(size_t)row * ldc + col]       = v0;
            *(float2*)&C[(size_t)(row + 8) * ldc + col] = v1;
        }
}

// ===========================================================================
// Attention scores via mma: per (b,h) TN GEMM Q[256,64] x K[1024,64]^T.
// Split-3 over K=64 -> 6 slabs. grid (2, 8, 64). smem = 4 x 20480.
// Epilogue: *0.125, mask, write fp32 g_att[(z*S+s)*SKV + k].
// ===========================================================================
__global__ void __launch_bounds__(256, 2) attn_scores_mma(const int* __restrict__ mask)
{
    extern __shared__ char smem[];
    const uint32_t sbase = smem_u32(smem);
    const int tid  = threadIdx.x;
    const int lane = tid & 31;
    const int warp = tid >> 5;
    const int wm   = warp >> 1, wn = warp & 1;
    const int g    = lane >> 2, t4 = lane & 3;
    const int m0   = blockIdx.x * 128;
    const int n0   = blockIdx.y * 128;
    const int z    = blockIdx.z;
    const int b    = z >> 3, h = z & 7;

    const size_t aoff = ((size_t)b * S_)   * H_ + h * HD_;
    const size_t boff = ((size_t)b * SKV_) * H_ + h * HD_;

    float acc[2][8][4];
#pragma unroll
    for (int mi = 0; mi < 2; mi++)
#pragma unroll
        for (int ni = 0; ni < 8; ni++)
#pragma unroll
            for (int f = 0; f < 4; f++) acc[mi][ni][f] = 0.f;

    const int c0r = (tid)       >> 2, c0k = ((tid)       & 3) * 8;
    const int c1r = (tid + 256) >> 2, c1k = ((tid + 256) & 3) * 8;

    const int lm_row = lane & 15;
    const int lm_col = (lane >> 4) * 16;

    auto issue = [&](int t, int buf) {
        const int seg  = t >> 1;                       // 0,1,2
        const int kofs = (t & 1) * 32;
        const __nv_bfloat16* Ap = (seg < 2)  ? g_Qhi : g_Qlo;
        const __nv_bfloat16* Bp = (seg == 1) ? g_Klo : g_Khi;
        const uint32_t sA = sbase + buf * LGS_STAGE;
        const uint32_t sB = sA + LGS_BOFF;
        CP_ASYNC16(sA + c0r * 80 + c0k * 2, Ap + aoff + (size_t)(m0 + c0r) * H_ + kofs + c0k);
        CP_ASYNC16(sA + c1r * 80 + c1k * 2, Ap + aoff + (size_t)(m0 + c1r) * H_ + kofs + c1k);
        CP_ASYNC16(sB + c0r * 80 + c0k * 2, Bp + boff + (size_t)(n0 + c0r) * H_ + kofs + c0k);
        CP_ASYNC16(sB + c1r * 80 + c1k * 2, Bp + boff + (size_t)(n0 + c1r) * H_ + kofs + c1k);
    };

    issue(0, 0); CP_COMMIT();
    issue(1, 1); CP_COMMIT();
    issue(2, 2); CP_COMMIT();

    for (int t = 0; t < 6; t++) {
        if (t + 2 < 6)      { CP_WAIT2(); }
        else if (t + 1 < 6) { CP_WAIT1(); }
        else                { CP_WAIT0(); }
        __syncthreads();
        if (t + 3 < 6) { issue(t + 3, (t + 3) & 3); CP_COMMIT(); }

        const uint32_t sA = sbase + (t & 3) * LGS_STAGE;
        const uint32_t sB = sA + LGS_BOFF;

#pragma unroll
        for (int k0 = 0; k0 < 2; k0++) {
            const uint32_t kb = k0 * 32 + lm_col;
            uint32_t a[2][4];
#pragma unroll
            for (int mi = 0; mi < 2; mi++) {
                uint32_t addr = sA + (uint32_t)(wm * 32 + mi * 16 + lm_row) * 80 + kb;
                LDMATRIX_X4(a[mi][0], a[mi][1], a[mi][2], a[mi][3], addr);
            }
            uint32_t bf[4][4];
#pragma unroll
            for (int nj = 0; nj < 4; nj++) {
                uint32_t addr = sB + (uint32_t)(wn * 64 + nj * 16 + lm_row) * 80 + kb;
                LDMATRIX_X4(bf[nj][0], bf[nj][1], bf[nj][2], bf[nj][3], addr);
            }
#pragma unroll
            for (int nj = 0; nj < 4; nj++)
#pragma unroll
                for (int hh = 0; hh < 2; hh++) {
                    const int ni = nj * 2 + hh;
#pragma unroll
                    for (int mi = 0; mi < 2; mi++)
                        MMA16816(acc[mi][ni], a[mi], bf[nj][hh], bf[nj][hh + 2]);
                }
        }
    }

    const float scale = 0.125f;
#pragma unroll
    for (int mi = 0; mi < 2; mi++)
#pragma unroll
        for (int ni = 0; ni < 8; ni++) {
            int row = m0 + wm * 32 + mi * 16 + g;
            int col = n0 + wn * 64 + ni * 8 + 2 * t4;
            bool ok0 = mask[b * SKV_ + col]     == 1;
            bool ok1 = mask[b * SKV_ + col + 1] == 1;
            float2 v0 = make_float2(ok0 ? acc[mi][ni][0]*scale : -1e9f,
                                    ok1 ? acc[mi][ni][1]*scale : -1e9f);
            float2 v1 = make_float2(ok0 ? acc[mi][ni][2]*scale : -1e9f,
                                    ok1 ? acc[mi][ni][3]*scale : -1e9f);
            *(float2*)&g_att[((size_t)z * S_ + row)     * SKV_ + col] = v0;
            *(float2*)&g_att[((size_t)z * S_ + row + 8) * SKV_ + col] = v1;
        }
}

// ===========================================================================
// Softmax over SKV=1024 -> writes bf16 hi/lo attention weights
// ===========================================================================
__global__ void __launch_bounds__(128) softmax_k()
{
    const size_t base = (size_t)blockIdx.x * SKV_;
    const int tid = threadIdx.x;
    float v[8];
    float mx = -1e30f;
#pragma unroll
    for (int i = 0; i < 8; i++) {
        v[i] = g_att[base + tid + i * 128];
        mx = fmaxf(mx, v[i]);
    }
    __shared__ float sm[4];
#pragma unroll
    for (int off = 16; off > 0; off >>= 1)
        mx = fmaxf(mx, __shfl_xor_sync(0xffffffffu, mx, off));
    if ((tid & 31) == 0) sm[tid >> 5] = mx;
    __syncthreads();
    mx = fmaxf(fmaxf(sm[0], sm[1]), fmaxf(sm[2], sm[3]));

    float sum = 0.f;
#pragma unroll
    for (int i = 0; i < 8; i++) { v[i] = expf(v[i] - mx); sum += v[i]; }
#pragma unroll
    for (int off = 16; off > 0; off >>= 1)
        sum += __shfl_xor_sync(0xffffffffu, sum, off);
    __syncthreads();
    if ((tid & 31) == 0) sm[tid >> 5] = sum;
    __syncthreads();
    sum = sm[0] + sm[1] + sm[2] + sm[3];
    const float inv = 1.f / sum;
#pragma unroll
    for (int i = 0; i < 8; i++) {
        float w = v[i] * inv;
        __nv_bfloat16 hh, ll;
        split2(w, hh, ll);
        g_atth[base + tid + i * 128] = hh;
        g_attl[base + tid + i * 128] = ll;
    }
}

// ===========================================================================
// V transpose + split: VT[b][c][k] = V[b][k][c], fp32 -> bf16 hi/lo.
// grid (H/32, SKV/32, B), block 256 (32x8).
// ===========================================================================
__global__ void __launch_bounds__(256) vt_split_k()
{
    __shared__ float sm[32][33];
    const int c0 = blockIdx.x * 32;
    const int k0 = blockIdx.y * 32;
    const int b  = blockIdx.z;
    const int tx = threadIdx.x & 31, ty = threadIdx.x >> 5;   // ty 0..7

#pragma unroll
    for (int j = 0; j < 4; j++) {
        int k = ty + j * 8;
        sm[k][tx] = g_V[((size_t)b * SKV_ + k0 + k) * H_ + c0 + tx];
    }
    __syncthreads();
#pragma unroll
    for (int j = 0; j < 4; j++) {
        int c = ty + j * 8;
        float v = sm[tx][c];
        __nv_bfloat16 hh, ll;
        split2(v, hh, ll);
        size_t o = ((size_t)b * H_ + c0 + c) * SKV_ + k0 + tx;
        g_VThi[o] = hh;
        g_VTlo[o] = ll;
    }
}

// ===========================================================================
// attn @ V via mma: per (b,h) TN GEMM att[256,1024] x VT[64,1024]^T.
// Split-3 -> 96 slabs. Tile 128(m) x 64(n). grid (2, 64). smem 4x15360.
// ===========================================================================
#define CTX_STAGE 15360
#define CTX_BOFF  10240
#define CTX_SMEM  (4 * CTX_STAGE)

__global__ void __launch_bounds__(256, 2) attn_ctx_mma()
{
    extern __shared__ char smem[];
    const uint32_t sbase = smem_u32(smem);
    const int tid  = threadIdx.x;
    const int lane = tid & 31;
    const int warp = tid >> 5;
    const int wm   = warp >> 1, wn = warp & 1;   // 4m x 2n, warp tile 32x32
    const int g    = lane >> 2, t4 = lane & 3;
    const int m0   = blockIdx.x * 128;
    const int z    = blockIdx.y;
    const int b    = z >> 3, h = z & 7;

    const size_t aoff = (size_t)z * S_ * SKV_;                  // att [z][s][k]
    const size_t boff = ((size_t)b * H_ + h * HD_) * SKV_;      // VT  [b][h*64+d][k]

    float acc[2][4][4];
#pragma unroll
    for (int mi = 0; mi < 2; mi++)
#pragma unroll
        for (int ni = 0; ni < 4; ni++)
#pragma unroll
            for (int f = 0; f < 4; f++) acc[mi][ni][f] = 0.f;

    // A: 512 chunks (2/thread), B: 256 chunks (1/thread)
    const int a0r = (tid)       >> 2, a0k = ((tid)       & 3) * 8;
    const int a1r = (tid + 256) >> 2, a1k = ((tid + 256) & 3) * 8;
    const int bro = tid >> 2,         brk = (tid & 3) * 8;      // row 0..63

    const int lm_row = lane & 15;
    const int lm_col = (lane >> 4) * 16;

    auto issue = [&](int t, int buf) {
        const int seg  = t >> 5;                     // 0,1,2  (32 slabs each)
        const int kofs = (t & 31) * 32;
        const __nv_bfloat16* Ap = (seg < 2)  ? g_atth : g_attl;
        const __nv_bfloat16* Bp = (seg == 1) ? g_VTlo : g_VThi;
        const uint32_t sA = sbase + buf * CTX_STAGE;
        const uint32_t sB = sA + CTX_BOFF;
        CP_ASYNC16(sA + a0r * 80 + a0k * 2, Ap + aoff + (size_t)(m0 + a0r) * SKV_ + kofs + a0k);
        CP_ASYNC16(sA + a1r * 80 + a1k * 2, Ap + aoff + (size_t)(m0 + a1r) * SKV_ + kofs + a1k);
        CP_ASYNC16(sB + bro * 80 + brk * 2, Bp + boff + (size_t)bro * SKV_ + kofs + brk);
    };

    issue(0, 0); CP_COMMIT();
    issue(1, 1); CP_COMMIT();
    issue(2, 2); CP_COMMIT();

    for (int t = 0; t < 96; t++) {
        if (t < 94)       { CP_WAIT2(); }
        else if (t == 94) { CP_WAIT1(); }
        else              { CP_WAIT0(); }
        __syncthreads();
        if (t + 3 < 96) { issue(t + 3, (t + 3) & 3); CP_COMMIT(); }

        const uint32_t sA = sbase + (t & 3) * CTX_STAGE;
        const uint32_t sB = sA + CTX_BOFF;

#pragma unroll
        for (int k0 = 0; k0 < 2; k0++) {
            const uint32_t kb = k0 * 32 + lm_col;
            uint32_t a[2][4];
#pragma unroll
            for (int mi = 0; mi < 2; mi++) {
                uint32_t addr = sA + (uint32_t)(wm * 32 + mi * 16 + lm_row) * 80 + kb;
                LDMATRIX_X4(a[mi][0], a[mi][1], a[mi][2], a[mi][3], addr);
            }
            uint32_t bf[2][4];
#pragma unroll
            for (int nj = 0; nj < 2; nj++) {
                uint32_t addr = sB + (uint32_t)(wn * 32 + nj * 16 + lm_row) * 80 + kb;
                LDMATRIX_X4(bf[nj][0], bf[nj][1], bf[nj][2], bf[nj][3], addr);
            }
#pragma unroll
            for (int nj = 0; nj < 2; nj++)
#pragma unroll
                for (int hh = 0; hh < 2; hh++) {
                    const int ni = nj * 2 + hh;
#pragma unroll
                    for (int mi = 0; mi < 2; mi++)
                        MMA16816(acc[mi][ni], a[mi], bf[nj][hh], bf[nj][hh + 2]);
                }
        }
    }

#pragma unroll
    for (int mi = 0; mi < 2; mi++)
#pragma unroll
        for (int ni = 0; ni < 4; ni++) {
            int row = m0 + wm * 32 + mi * 16 + g;
            int col = wn * 32 + ni * 8 + 2 * t4;               // 0..63 within head
            float2 v0 = make_float2(acc[mi][ni][0], acc[mi][ni][1]);
            float2 v1 = make_float2(acc[mi][ni][2], acc[mi][ni][3]);
            *(float2*)&g_ctx[((size_t)b * S_ + row)     * H_ + h * HD_ + col] = v0;
            *(float2*)&g_ctx[((size_t)b * S_ + row + 8) * H_ + h * HD_ + col] = v1;
        }
}

// ===========================================================================
// Reset kernel
// ===========================================================================
__global__ void reset_k()
{
    if (threadIdx.x < 4) g_arrive[threadIdx.x] = 0u;
}

// ===========================================================================
// Persistent LSTM recurrence (unchanged, passing)
// ===========================================================================
__device__ __forceinline__ float sigm(float x) { return 1.f / (1.f + expf(-x)); }

__global__ void __launch_bounds__(256, 1) rnn_kernel(
    const float* __restrict__ W_hh, const float* __restrict__ h0,
    const float* __restrict__ c0)
{
    const int cta  = blockIdx.x;
    const int pair = cta >> 5;
    const int grp  = cta & 31;
    const int tid  = threadIdx.x;
    const int q    = tid >> 6;
    const int r    = tid & 63;
    const int gate = r >> 4, uu = r & 15;
    const int unit = grp * 16 + uu;

    __shared__ float h_sm[2][H_];
    __shared__ float red[4][64][2];
    __shared__ float gsm[64][2];
    __shared__ float c_sm[2][16];

    float w[128];
    {
        const float4* wp = (const float4*)(W_hh + (size_t)(gate * H_ + unit) * H_ + q * 128);
#pragma unroll
        for (int j = 0; j < 32; j++) {
            float4 v = wp[j];
            w[4*j+0] = v.x; w[4*j+1] = v.y; w[4*j+2] = v.z; w[4*j+3] = v.w;
        }
    }

    for (int s = 0; s < S_; s++) {
        {
            const int bb = tid >> 7, off = (tid & 127) * 4;
            float4 v;
            if (s == 0) v = *(const float4*)(h0 + (size_t)(pair*2 + bb) * H_ + off);
            else        v = __ldcg((const float4*)(g_hcur + (size_t)(pair*2 + bb) * H_ + off));
            *(float4*)&h_sm[bb][off] = v;
        }
        if (s == 0 && tid < 32) {
            int b2 = tid >> 4, u2 = tid & 15;
            c_sm[b2][u2] = c0[(size_t)(pair*2 + b2) * H_ + grp*16 + u2];
        }
        __syncthreads();

        float a0 = 0.f, a1 = 0.f;
        {
            const float* hp0 = &h_sm[0][q * 128];
            const float* hp1 = &h_sm[1][q * 128];
#pragma unroll
            for (int j = 0; j < 128; j++) {
                a0 += w[j] * hp0[j];
                a1 += w[j] * hp1[j];
            }
        }
        red[q][r][0] = a0;
        red[q][r][1] = a1;
        __syncthreads();

        if (tid < 128) {
            const int rr = tid >> 1, bb = tid & 1;
            const int gg = rr >> 4, u2 = rr & 15;
            float g = red[0][rr][bb] + red[1][rr][bb] + red[2][rr][bb] + red[3][rr][bb]
                    + g_xg[((size_t)(pair*2 + bb) * S_ + s) * G4_ + gg * H_ + grp*16 + u2];
            gsm[rr][bb] = g;
        }
        __syncthreads();

        if (tid < 32) {
            const int bb = tid >> 4, u2 = tid & 15;
            float iv = gsm[ 0 + u2][bb];
            float fv = gsm[16 + u2][bb];
            float gv = gsm[32 + u2][bb];
            float ov = gsm[48 + u2][bb];
            float cn = sigm(fv) * c_sm[bb][u2] + sigm(iv) * tanhf(gv);
            float hn = sigm(ov) * tanhf(cn);
            c_sm[bb][u2] = cn;
            const int bg = pair*2 + bb, un = grp*16 + u2;
            g_hcur[(size_t)bg * H_ + un] = hn;
            g_H[((size_t)bg * S_ + s) * H_ + un] = hn;
            __threadfence();
        }
        __syncthreads();

        if (tid == 0) {
            atomicAdd(&g_arrive[pair], 1u);
            const unsigned target = 32u * (unsigned)(s + 1);
            while (*((volatile unsigned*)&g_arrive[pair]) < target) { }
        }
        __syncthreads();
        __threadfence();
    }
}

// ===========================================================================
// Host orchestration
// ===========================================================================
extern "C" void kernel_launch(void* const* d_in, const int* in_sizes, int n_in,
                              void* d_out, int out_size)
{
    const int*   tok   = (const int*)  d_in[0];
    const float* enc   = (const float*)d_in[1];
    const int*   mask  = (const int*)  d_in[2];
    const float* emb   = (const float*)d_in[3];
    const float* W_ih  = (const float*)d_in[4];
    const float* W_hh  = (const float*)d_in[5];
    const float* b_ih  = (const float*)d_in[6];
    const float* b_hh  = (const float*)d_in[7];
    const float* Wq    = (const float*)d_in[8];
    const float* bq    = (const float*)d_in[9];
    const float* Wk    = (const float*)d_in[10];
    const float* bk    = (const float*)d_in[11];
    const float* Wv    = (const float*)d_in[12];
    const float* bv    = (const float*)d_in[13];
    const float* Wo    = (const float*)d_in[14];
    const float* bo    = (const float*)d_in[15];
    const float* h0    = (const float*)d_in[16];
    const float* c0    = (const float*)d_in[17];
    float* out = (float*)d_out;

    float *p_xg, *p_K, *p_V, *p_H, *p_Q, *p_ctx, *p_outs;
    cudaGetSymbolAddress((void**)&p_xg,   g_xg);
    cudaGetSymbolAddress((void**)&p_K,    g_K);
    cudaGetSymbolAddress((void**)&p_V,    g_V);
    cudaGetSymbolAddress((void**)&p_H,    g_H);
    cudaGetSymbolAddress((void**)&p_Q,    g_Q);
    cudaGetSymbolAddress((void**)&p_ctx,  g_ctx);
    cudaGetSymbolAddress((void**)&p_outs, g_outs);

    __nv_bfloat16 *p_ehi, *p_elo, *p_ohi, *p_olo, *p_echi, *p_eclo;
    __nv_bfloat16 *p_wihhi, *p_wihlo, *p_wqhi, *p_wqlo, *p_wkhi, *p_wklo;
    __nv_bfloat16 *p_wvhi, *p_wvlo, *p_wohi, *p_wolo;
    __nv_bfloat16 *p_Hhi, *p_Hlo, *p_cxhi, *p_cxlo, *p_Qhi, *p_Qlo, *p_Khi, *p_Klo;
    cudaGetSymbolAddress((void**)&p_ehi,   g_embhi);
    cudaGetSymbolAddress((void**)&p_elo,   g_emblo);
    cudaGetSymbolAddress((void**)&p_ohi,   g_outhi);
    cudaGetSymbolAddress((void**)&p_olo,   g_outlo);
    cudaGetSymbolAddress((void**)&p_echi,  g_enchi);
    cudaGetSymbolAddress((void**)&p_eclo,  g_enclo);
    cudaGetSymbolAddress((void**)&p_wihhi, g_wihhi);
    cudaGetSymbolAddress((void**)&p_wihlo, g_wihlo);
    cudaGetSymbolAddress((void**)&p_wqhi,  g_wqhi);
    cudaGetSymbolAddress((void**)&p_wqlo,  g_wqlo);
    cudaGetSymbolAddress((void**)&p_wkhi,  g_wkhi);
    cudaGetSymbolAddress((void**)&p_wklo,  g_wklo);
    cudaGetSymbolAddress((void**)&p_wvhi,  g_wvhi);
    cudaGetSymbolAddress((void**)&p_wvlo,  g_wvlo);
    cudaGetSymbolAddress((void**)&p_wohi,  g_wohi);
    cudaGetSymbolAddress((void**)&p_wolo,  g_wolo);
    cudaGetSymbolAddress((void**)&p_Hhi,   g_Hhi);
    cudaGetSymbolAddress((void**)&p_Hlo,   g_Hlo);
    cudaGetSymbolAddress((void**)&p_cxhi,  g_ctxhi);
    cudaGetSymbolAddress((void**)&p_cxlo,  g_ctxlo);
    cudaGetSymbolAddress((void**)&p_Qhi,   g_Qhi);
    cudaGetSymbolAddress((void**)&p_Qlo,   g_Qlo);
    cudaGetSymbolAddress((void**)&p_Khi,   g_Khi);
    cudaGetSymbolAddress((void**)&p_Klo,   g_Klo);

    cudaFuncSetAttribute(hgemm_tn_mma,
                         cudaFuncAttributeMaxDynamicSharedMemorySize, LGS_SMEM);
    cudaFuncSetAttribute(attn_scores_mma,
                         cudaFuncAttributeMaxDynamicSharedMemorySize, LGS_SMEM);
    cudaFuncSetAttribute(attn_ctx_mma,
                         cudaFuncAttributeMaxDynamicSharedMemorySize, CTX_SMEM);

    reset_k<<<1, 32>>>();

    // ---- input splits ----
    split_bf16_k<<<(V_*H_/4 + 1023)/1024, 256>>>(emb,  p_ehi,   p_elo,   V_*H_/4);
    split_bf16_k<<<(BKV_*H_/4 + 1023)/1024, 256>>>(enc, p_echi, p_eclo, BKV_*H_/4);
    split_bf16_k<<<(G4_*H_/4 + 1023)/1024, 256>>>(W_ih, p_wihhi, p_wihlo, G4_*H_/4);
    split_bf16_k<<<(H_*H_/4 + 1023)/1024, 256>>>(Wq,   p_wqhi,  p_wqlo,  H_*H_/4);
    split_bf16_k<<<(H_*H_/4 + 1023)/1024, 256>>>(Wk,   p_wkhi,  p_wklo,  H_*H_/4);
    split_bf16_k<<<(H_*H_/4 + 1023)/1024, 256>>>(Wv,   p_wvhi,  p_wvlo,  H_*H_/4);
    split_bf16_k<<<(H_*H_/4 + 1023)/1024, 256>>>(Wo,   p_wohi,  p_wolo,  H_*H_/4);

    // ---- x-gates (gather), K/V projections ----
    hgemm_tn_mma<<<dim3(BT_/128, G4_/128), 256, LGS_SMEM>>>(
        G4_, p_ehi, p_elo, tok, p_wihhi, p_wihlo, b_ih, b_hh, p_xg);
    hgemm_tn_mma<<<dim3(BKV_/128, H_/128), 256, LGS_SMEM>>>(
        H_, p_echi, p_eclo, nullptr, p_wkhi, p_wklo, bk, nullptr, p_K);
    hgemm_tn_mma<<<dim3(BKV_/128, H_/128), 256, LGS_SMEM>>>(
        H_, p_echi, p_eclo, nullptr, p_wvhi, p_wvlo, bv, nullptr, p_V);

    // ---- serial LSTM recurrence ----
    rnn_kernel<<<128, 256>>>(W_hh, h0, c0);

    // ---- Q projection ----
    split_bf16_k<<<(BT_*H_/4 + 1023)/1024, 256>>>(p_H, p_Hhi, p_Hlo, BT_*H_/4);
    hgemm_tn_mma<<<dim3(BT_/128, H_/128), 256, LGS_SMEM>>>(
        H_, p_Hhi, p_Hlo, nullptr, p_wqhi, p_wqlo, bq, nullptr, p_Q);

    // ---- attention (tensor-core path) ----
    split_bf16_k<<<(BT_*H_/4 + 1023)/1024, 256>>>(p_Q, p_Qhi, p_Qlo, BT_*H_/4);
    split_bf16_k<<<(BKV_*H_/4 + 1023)/1024, 256>>>(p_K, p_Khi, p_Klo, BKV_*H_/4);
    vt_split_k<<<dim3(H_/32, SKV_/32, B_), 256>>>();
    attn_scores_mma<<<dim3(2, 8, 64), 256, LGS_SMEM>>>(mask);
    softmax_k<<<B_*NH_*S_, 128>>>();
    attn_ctx_mma<<<dim3(2, 64), 256, CTX_SMEM>>>();

    // ---- output projection ----
    split_bf16_k<<<(BT_*H_/4 + 1023)/1024, 256>>>(p_ctx, p_cxhi, p_cxlo, BT_*H_/4);
    hgemm_tn_mma<<<dim3(BT_/128, H_/128), 256, LGS_SMEM>>>(
        H_, p_cxhi, p_cxlo, nullptr, p_wohi, p_wolo, bo, nullptr, p_outs);

    // ---- tied logits ----
    split_bf16_k<<<(BT_*H_/4 + 1023)/1024, 256>>>(p_outs, p_ohi, p_olo, BT_*H_/4);
    hgemm_tn_mma<<<dim3(BT_/128, V_/128), 256, LGS_SMEM>>>(
        V_, p_ohi, p_olo, nullptr, p_ehi, p_elo, nullptr, nullptr, out);
}